// round 14
// baseline (speedup 1.0000x reference)
#include <cuda_runtime.h>
#include <math.h>

// ---------------- problem constants ----------------
namespace {
constexpr int D_   = 550;
constexpr int LDP  = 560;    // padded lead dim: 35*16, all pads guaranteed zero
constexpr int MATR = 640;    // matrix buffer rows (5*128 tile coverage, zero pads)
constexpr int F_   = 275;
constexpr int LDF  = 288;    // padded ident stride (36*8, zero pads -> guard-free K)
constexpr int B_   = 4096;   // N*T = 8*512
constexpr int H_   = 128;
constexpr int OUT_ = 6325;   // F_*(3*8-1)
constexpr int LDW  = 6720;   // padded Wo cols: 280 features * 24
}

// ---------------- scratch (device globals; no allocs allowed) ----------------
__device__ float g_z  [B_*LDP];   // zero-init => pad cols stay 0
__device__ float g_zn [B_*LDP];
__device__ float g_LT [MATR*LDP]; // rows >= 550 stay zero
__device__ float g_UpT[MATR*LDP]; // rows >= 550 stay zero
__device__ float g_ApT[MATR*LDP]; // stored tf32-rounded
__device__ float g_id [B_*LDF];   // stored tf32-rounded; zero-init pads
__device__ float g_t  [B_*H_];
__device__ float g_lq [B_];
__device__ float g_slog[3];
__device__ float g_kn [F_*27];    // per-f ident knots
__device__ float g_Wop[H_*LDW];   // padded Wo, tf32-rounded
__device__ float g_Wip[288*H_];   // padded Wi, tf32-rounded
__device__ float g_Wbp[4*H_*H_];  // Wb, tf32-rounded

// ---------------- helpers ----------------
__device__ __forceinline__ float softplus_acc(float x) {
    return (x > 20.f) ? x : log1pf(__expf(x));
}
__device__ __forceinline__ float softplus_fast(float x) {
    return (x > 15.f) ? x : __logf(1.f + __expf(x));
}

__device__ __forceinline__ unsigned f2tf32(float x) {
    unsigned r; asm("cvt.rna.tf32.f32 %0, %1;" : "=r"(r) : "f"(x)); return r;
}
__device__ __forceinline__ float roundtf(float x) {
    return __uint_as_float(f2tf32(x));
}

__device__ __forceinline__ void mma_tf32(float* c,
    unsigned a0, unsigned a1, unsigned a2, unsigned a3,
    unsigned b0, unsigned b1)
{
    asm volatile(
        "mma.sync.aligned.m16n8k8.row.col.f32.tf32.tf32.f32 "
        "{%0,%1,%2,%3}, {%4,%5,%6,%7}, {%8,%9}, {%0,%1,%2,%3};\n"
        : "+f"(c[0]), "+f"(c[1]), "+f"(c[2]), "+f"(c[3])
        : "r"(a0), "r"(a1), "r"(a2), "r"(a3), "r"(b0), "r"(b1));
}

__device__ __forceinline__ float block_reduce_sum(float v) {
    __shared__ float sred[32];
    int tid = threadIdx.x;
    #pragma unroll
    for (int o = 16; o > 0; o >>= 1) v += __shfl_down_sync(0xffffffffu, v, o);
    if ((tid & 31) == 0) sred[tid >> 5] = v;
    __syncthreads();
    if (tid < 32) {
        int nw = (blockDim.x + 31) >> 5;
        v = (tid < nw) ? sred[tid] : 0.f;
        #pragma unroll
        for (int o = 16; o > 0; o >>= 1) v += __shfl_down_sync(0xffffffffu, v, o);
    }
    return v;
}

// Fast inverse RQS, params in registers (conditional path).
__device__ __forceinline__ void rqs_fast(float x, const float* uw, const float* uh,
                                         const float* ud7, float& out, float& ld)
{
    const float TB = 3.f;
    bool inside = (x >= -TB) && (x <= TB);
    float xi = fminf(fmaxf(x, -TB), TB);

    float cw[9], ch[9];
    {
        float m = uw[0];
        #pragma unroll
        for (int k = 1; k < 8; k++) m = fmaxf(m, uw[k]);
        float e[8]; float s = 0.f;
        #pragma unroll
        for (int k = 0; k < 8; k++) { e[k] = __expf(uw[k] - m); s += e[k]; }
        float inv = __fdividef(1.f, s);
        float cum = 0.f;
        cw[0] = -TB;
        #pragma unroll
        for (int k = 0; k < 7; k++) { cum += 0.001f + 0.992f * e[k] * inv; cw[k+1] = 6.f * cum - 3.f; }
        cw[8] = TB;
    }
    {
        float m = uh[0];
        #pragma unroll
        for (int k = 1; k < 8; k++) m = fmaxf(m, uh[k]);
        float e[8]; float s = 0.f;
        #pragma unroll
        for (int k = 0; k < 8; k++) { e[k] = __expf(uh[k] - m); s += e[k]; }
        float inv = __fdividef(1.f, s);
        float cum = 0.f;
        ch[0] = -TB;
        #pragma unroll
        for (int k = 0; k < 7; k++) { cum += 0.001f + 0.992f * e[k] * inv; ch[k+1] = 6.f * cum - 3.f; }
        ch[8] = TB;
    }

    int cnt = 0;
    #pragma unroll
    for (int k = 0; k < 9; k++) {
        float lo = ch[k] + (k == 8 ? 1e-6f : 0.f);
        cnt += (xi >= lo) ? 1 : 0;
    }
    int idx = cnt - 1; idx = idx < 0 ? 0 : (idx > 7 ? 7 : idx);

    float icw = 0.f, iw = 1.f, ich = 0.f, ih = 1.f;
    float u0 = 0.f, u1 = 0.f;
    #pragma unroll
    for (int k = 0; k < 8; k++) {
        if (k == idx) {
            icw = cw[k]; iw = cw[k+1] - cw[k];
            ich = ch[k]; ih = ch[k+1] - ch[k];
        }
    }
    #pragma unroll
    for (int k = 0; k < 7; k++) {
        if (k == idx - 1) u0 = ud7[k];
        if (k == idx)     u1 = ud7[k];
    }
    float d0 = (idx == 0) ? 1.f : 0.001f + softplus_fast(u0);
    float d1 = (idx == 7) ? 1.f : 0.001f + softplus_fast(u1);

    float delta = __fdividef(ih, iw);
    float t  = xi - ich;
    float s2 = d0 + d1 - 2.f * delta;
    float aa = t * s2 + ih * (delta - d0);
    float bb = ih * d0 - t * s2;
    float cc = -delta * t;
    float disc = bb * bb - 4.f * aa * cc;
    float sq = disc * __frsqrt_rn(fmaxf(disc, 1e-37f));
    float root = __fdividef(2.f * cc, -bb - sq);
    float o = root * iw + icw;
    float tm = root * (1.f - root);
    float den = delta + s2 * tm;
    float omr = 1.f - root;
    float dnum = delta * delta * (d1 * root * root + 2.f * delta * tm + d0 * omr * omr);
    float l = -__logf(__fdividef(dnum, den * den));

    out = inside ? o : x;
    ld  = inside ? l : 0.f;
}

// ---------------- small kernels ----------------
__global__ void zero_kernel(float* p, int n) {
    int i = blockIdx.x * blockDim.x + threadIdx.x;
    if (i < n) p[i] = 0.f;
}

__global__ void copy_pad_kernel(const float* __restrict__ x, float* __restrict__ z) {
    int i = blockIdx.x * blockDim.x + threadIdx.x;
    if (i >= B_ * D_) return;
    int b = i / D_, d = i % D_;
    z[b * LDP + d] = x[i];
}

__global__ void sumlog_kernel(const float* __restrict__ lu_ud, float* __restrict__ out) {
    int i = blockIdx.x;
    float s = 0.f;
    for (int d = threadIdx.x; d < D_; d += blockDim.x)
        s += __logf(softplus_acc(lu_ud[i * D_ + d]) + 0.001f);
    s = block_reduce_sum(s);
    if (threadIdx.x == 0) out[i] = s;
}

// Combined per-layer weight prep (tf32-rounded at materialization).
__global__ void prep_weights_kernel(const float* __restrict__ Wi,
                                    const float* __restrict__ Wb,
                                    const float* __restrict__ Wo,
                                    float* __restrict__ Wip,
                                    float* __restrict__ Wbp,
                                    float* __restrict__ Wop)
{
    constexpr int N_WIP = 288 * H_;
    constexpr int N_WBP = 4 * H_ * H_;
    constexpr int N_WOP = H_ * LDW;
    int idx = blockIdx.x * blockDim.x + threadIdx.x;
    if (idx < N_WIP) {
        int f = idx / H_, h = idx % H_;
        Wip[idx] = (f < F_) ? roundtf(Wi[f * H_ + h]) : 0.f;
    } else if (idx < N_WIP + N_WBP) {
        int j = idx - N_WIP;
        Wbp[j] = roundtf(Wb[j]);
    } else if (idx < N_WIP + N_WBP + N_WOP) {
        int j = idx - N_WIP - N_WBP;
        int k = j / LDW, c = j % LDW;
        int f = c / 24, o = c % 24;
        float v = 0.f;
        if (o < 23 && f < F_) v = roundtf(Wo[k * OUT_ + f * 23 + o]);
        Wop[j] = v;
    }
}

// Per-f knots for the unconditional (ident) spline
__global__ void ident_knots_kernel(const float* __restrict__ uw_u,
                                   const float* __restrict__ uh_u,
                                   const float* __restrict__ ud_u,
                                   float* __restrict__ kn)
{
    int f = blockIdx.x * blockDim.x + threadIdx.x;
    if (f >= F_) return;
    const float TB = 3.f;
    float* o = kn + f * 27;
    {
        const float* u = uw_u + f * 8;
        float m = u[0];
        #pragma unroll
        for (int k = 1; k < 8; k++) m = fmaxf(m, u[k]);
        float e[8]; float s = 0.f;
        #pragma unroll
        for (int k = 0; k < 8; k++) { e[k] = __expf(u[k] - m); s += e[k]; }
        float inv = 1.f / s;
        float cum = 0.f;
        o[0] = -TB;
        #pragma unroll
        for (int k = 0; k < 7; k++) { cum += 0.001f + 0.992f * e[k] * inv; o[k+1] = 6.f * cum - 3.f; }
        o[8] = TB;
    }
    {
        const float* u = uh_u + f * 8;
        float m = u[0];
        #pragma unroll
        for (int k = 1; k < 8; k++) m = fmaxf(m, u[k]);
        float e[8]; float s = 0.f;
        #pragma unroll
        for (int k = 0; k < 8; k++) { e[k] = __expf(u[k] - m); s += e[k]; }
        float inv = 1.f / s;
        float cum = 0.f;
        o[9] = -TB;
        #pragma unroll
        for (int k = 0; k < 7; k++) { cum += 0.001f + 0.992f * e[k] * inv; o[10+k] = 6.f * cum - 3.f; }
        o[17] = TB;
    }
    o[18] = 1.f; o[26] = 1.f;
    #pragma unroll
    for (int k = 0; k < 7; k++) o[19 + k] = 0.001f + softplus_acc(ud_u[f * 7 + k]);
}

// Table-driven ident spline eval. Block = 32 f x 8 b (256 thr).
__global__ void __launch_bounds__(256)
ident_eval_kernel(const float* __restrict__ zn, const float* __restrict__ kn,
                  float* __restrict__ ident, float* __restrict__ zout,
                  float* __restrict__ lq)
{
    __shared__ float sk[32][29];
    int tid = threadIdx.x;
    int f_local = tid & 31;
    int b_local = tid >> 5;
    int f0 = blockIdx.x * 32;
    int b  = blockIdx.y * 8 + b_local;

    for (int j = tid; j < 32 * 27; j += 256) {
        int fl = j / 27, e = j % 27;
        int f = f0 + fl;
        sk[fl][e] = (f < F_) ? kn[f * 27 + e] : 0.f;
    }
    __syncthreads();

    int f = f0 + f_local;
    float ldv = 0.f;
    if (f < F_) {
        const float TB = 3.f;
        const float* K = sk[f_local];
        float x = zn[b * LDP + 2 * f];
        bool inside = (x >= -TB) && (x <= TB);
        float xi = fminf(fmaxf(x, -TB), TB);

        int cnt = 0;
        #pragma unroll
        for (int k = 0; k < 9; k++) {
            float lo = K[9 + k] + (k == 8 ? 1e-6f : 0.f);
            cnt += (xi >= lo) ? 1 : 0;
        }
        int idx = cnt - 1; idx = idx < 0 ? 0 : (idx > 7 ? 7 : idx);

        float icw = K[idx],     iw = K[idx + 1] - icw;
        float ich = K[9 + idx], ih = K[10 + idx] - ich;
        float d0  = K[18 + idx], d1 = K[19 + idx];

        float delta = __fdividef(ih, iw);
        float t  = xi - ich;
        float s2 = d0 + d1 - 2.f * delta;
        float aa = t * s2 + ih * (delta - d0);
        float bb = ih * d0 - t * s2;
        float cc = -delta * t;
        float disc = bb * bb - 4.f * aa * cc;
        float sq = disc * __frsqrt_rn(fmaxf(disc, 1e-37f));
        float root = __fdividef(2.f * cc, -bb - sq);
        float o = root * iw + icw;
        float tm = root * (1.f - root);
        float den = delta + s2 * tm;
        float omr = 1.f - root;
        float dnum = delta * delta * (d1 * root * root + 2.f * delta * tm + d0 * omr * omr);
        float l = -__logf(__fdividef(dnum, den * den));

        float ov = inside ? o : x;
        ldv = inside ? l : 0.f;
        ident[b * LDF + f] = roundtf(ov);
        zout[b * LDP + 2 * f] = ov;
    }
    #pragma unroll
    for (int o = 16; o > 0; o >>= 1) ldv += __shfl_xor_sync(0xffffffffu, ldv, o);
    if (f_local == 0) atomicAdd(&lq[b], ldv);
}

// Materialize LT[m,d] = L[d,m] (unit diag) and UpT[perm[k], m] = Udense[m,k].
__global__ void build_lt_upt_kernel(const float* __restrict__ lower,
                                    const float* __restrict__ upper,
                                    const float* __restrict__ lu_ud,
                                    const int* __restrict__ perm,
                                    float* __restrict__ LT, float* __restrict__ UpT)
{
    int c = blockIdx.x * blockDim.x + threadIdx.x;
    int rr = blockIdx.y;
    if (c >= D_) return;
    if (blockIdx.z == 0) {
        int m = rr, d = c;
        float v = (m < d) ? lower[d * D_ + m] : ((m == d) ? 1.f : 0.f);
        LT[m * LDP + d] = v;
    } else {
        int k = rr, m = c;
        float v;
        if (m < k)       v = upper[m * D_ + k];
        else if (m == k) v = softplus_acc(lu_ud[k]) + 0.001f;
        else             v = 0.f;
        UpT[perm[k] * LDP + m] = v;
    }
}

// ---------------- tf32 TC GEMM core (128m x 64n, double-buffered) ------------
// RND_B: round B operand in-loop (for fp32 B); HASB: bias; TFOUT: round output.
template<bool RND_B, bool HASB, bool TFOUT>
__device__ __forceinline__ void tc_gemm_128x64(
    const float* __restrict__ A, int lda,
    const float* __restrict__ Bm, int ldb,
    const float* __restrict__ bias, float* __restrict__ C, int ldc,
    int m0, int n0, int K, int Nvalid,
    float (*As)[128][20], float (*Bs)[16][72])
{
    int tid  = threadIdx.x;
    int warp = tid >> 5, lane = tid & 31;
    int mwarp = (warp & 3) * 32;
    int nwarp = (warp >> 2) * 32;
    int g = lane >> 2, t4 = lane & 3;

    int arow0 = tid >> 2,            acol = (tid & 3) << 2;
    int arow1 = (tid + 256) >> 2;
    int brow  = tid >> 4,            bcol = (tid & 15) << 2;

    float c[2][4][4];
    #pragma unroll
    for (int i = 0; i < 2; i++)
        #pragma unroll
        for (int j = 0; j < 4; j++)
            c[i][j][0] = c[i][j][1] = c[i][j][2] = c[i][j][3] = 0.f;

    float4 sA0, sA1, sB;
    auto fetch = [&](int kc) {
        sA0 = *reinterpret_cast<const float4*>(&A[(m0 + arow0) * lda + kc + acol]);
        sA1 = *reinterpret_cast<const float4*>(&A[(m0 + arow1) * lda + kc + acol]);
        sB  = *reinterpret_cast<const float4*>(&Bm[(kc + brow) * ldb + n0 + bcol]);
    };
    auto store = [&](int buf) {
        float4 v = sA0;
        v.x = roundtf(v.x); v.y = roundtf(v.y); v.z = roundtf(v.z); v.w = roundtf(v.w);
        *reinterpret_cast<float4*>(&As[buf][arow0][acol]) = v;
        v = sA1;
        v.x = roundtf(v.x); v.y = roundtf(v.y); v.z = roundtf(v.z); v.w = roundtf(v.w);
        *reinterpret_cast<float4*>(&As[buf][arow1][acol]) = v;
        float4 w = sB;
        if (RND_B) {
            w.x = roundtf(w.x); w.y = roundtf(w.y);
            w.z = roundtf(w.z); w.w = roundtf(w.w);
        }
        *reinterpret_cast<float4*>(&Bs[buf][brow][bcol]) = w;
    };

    int NIT = K / 16;
    fetch(0);
    store(0);
    __syncthreads();

    for (int it = 0; it < NIT; it++) {
        int buf = it & 1;
        if (it + 1 < NIT) fetch((it + 1) * 16);
        #pragma unroll
        for (int k8 = 0; k8 < 16; k8 += 8) {
            #pragma unroll
            for (int mf = 0; mf < 2; mf++) {
                int mb = mwarp + mf * 16;
                unsigned a0 = __float_as_uint(As[buf][mb + g][k8 + t4]);
                unsigned a1 = __float_as_uint(As[buf][mb + g + 8][k8 + t4]);
                unsigned a2 = __float_as_uint(As[buf][mb + g][k8 + t4 + 4]);
                unsigned a3 = __float_as_uint(As[buf][mb + g + 8][k8 + t4 + 4]);
                #pragma unroll
                for (int nf = 0; nf < 4; nf++) {
                    unsigned b0r = __float_as_uint(Bs[buf][k8 + t4][nwarp + nf * 8 + g]);
                    unsigned b1r = __float_as_uint(Bs[buf][k8 + t4 + 4][nwarp + nf * 8 + g]);
                    mma_tf32(c[mf][nf], a0, a1, a2, a3, b0r, b1r);
                }
            }
        }
        if (it + 1 < NIT) store(buf ^ 1);
        __syncthreads();
    }

    #pragma unroll
    for (int mf = 0; mf < 2; mf++) {
        int r0 = m0 + mwarp + mf * 16 + g;
        int r1 = r0 + 8;
        #pragma unroll
        for (int nf = 0; nf < 4; nf++) {
            int cA = n0 + nwarp + nf * 8 + t4 * 2;
            int cB = cA + 1;
            if (cA < Nvalid) {
                float v0 = c[mf][nf][0] + (HASB ? bias[cA] : 0.f);
                float v2 = c[mf][nf][2] + (HASB ? bias[cA] : 0.f);
                C[r0 * ldc + cA] = TFOUT ? roundtf(v0) : v0;
                C[r1 * ldc + cA] = TFOUT ? roundtf(v2) : v2;
            }
            if (cB < Nvalid) {
                float v1 = c[mf][nf][1] + (HASB ? bias[cB] : 0.f);
                float v3 = c[mf][nf][3] + (HASB ? bias[cB] : 0.f);
                C[r0 * ldc + cB] = TFOUT ? roundtf(v1) : v1;
                C[r1 * ldc + cB] = TFOUT ? roundtf(v3) : v3;
            }
        }
    }
}

// zn = src @ ApT + bias (ApT pre-rounded)
__global__ void __launch_bounds__(256)
lu_gemm_tc(const float* __restrict__ src, const float* __restrict__ ApT,
           const float* __restrict__ bias, float* __restrict__ C)
{
    __shared__ __align__(16) float As[2][128][20];
    __shared__ __align__(16) float Bs[2][16][72];
    tc_gemm_128x64<false, true, false>(
        src, LDP, ApT, LDP, bias, C, LDP,
        blockIdx.y * 128, blockIdx.x * 64, LDP, D_, As, Bs);
}

// ApT = UpT @ LT (both fp32, rounded in-loop; output rounded)
__global__ void __launch_bounds__(256)
apt_gemm_tc(const float* __restrict__ UpT, const float* __restrict__ LT,
            float* __restrict__ ApT)
{
    __shared__ __align__(16) float As[2][128][20];
    __shared__ __align__(16) float Bs[2][16][72];
    tc_gemm_128x64<true, false, true>(
        UpT, LDP, LT, LDP, nullptr, ApT, LDP,
        blockIdx.y * 128, blockIdx.x * 64, LDP, D_, As, Bs);
}

// ---------------- fused tf32 resnet: t = resnet(ident) per 32-row block ------
__global__ void __launch_bounds__(256)
resnet_fused(const float* __restrict__ ident, const float* __restrict__ Wip,
             const float* __restrict__ bi, const float* __restrict__ Wbp,
             const float* __restrict__ bb, float* __restrict__ tout)
{
    extern __shared__ float smf[];
    float (*Ts)[132] = reinterpret_cast<float(*)[132]>(smf);
    float (*Rs)[132] = reinterpret_cast<float(*)[132]>(smf + 32 * 132);
    float (*Ws)[136] = reinterpret_cast<float(*)[136]>(smf + 64 * 132);
    float (*As)[36]  = reinterpret_cast<float(*)[36]>(smf + 64 * 132 + 32 * 136);

    int tid = threadIdx.x, warp = tid >> 5, lane = tid & 31;
    int mw = (warp & 1) * 16;
    int nw = (warp >> 1) * 32;
    int m0 = blockIdx.x * 32;
    int g = lane >> 2, t4 = lane & 3;

    float c[4][4];

    #pragma unroll
    for (int i = 0; i < 4; i++) c[i][0] = c[i][1] = c[i][2] = c[i][3] = 0.f;

    for (int kc = 0; kc < 288; kc += 32) {
        __syncthreads();
        {
            int r = tid >> 3, c4 = (tid & 7) << 2;
            *reinterpret_cast<float4*>(&As[r][c4]) =
                *reinterpret_cast<const float4*>(&ident[(m0 + r) * LDF + kc + c4]);
        }
        #pragma unroll
        for (int i = 0; i < 4; i++) {
            int idx = tid + i * 256;
            int r = idx >> 5, c4 = (idx & 31) << 2;
            *reinterpret_cast<float4*>(&Ws[r][c4]) =
                *reinterpret_cast<const float4*>(&Wip[(kc + r) * H_ + c4]);
        }
        __syncthreads();
        #pragma unroll
        for (int k8 = 0; k8 < 32; k8 += 8) {
            unsigned a0 = __float_as_uint(As[mw + g][k8 + t4]);
            unsigned a1 = __float_as_uint(As[mw + g + 8][k8 + t4]);
            unsigned a2 = __float_as_uint(As[mw + g][k8 + t4 + 4]);
            unsigned a3 = __float_as_uint(As[mw + g + 8][k8 + t4 + 4]);
            #pragma unroll
            for (int nf = 0; nf < 4; nf++) {
                unsigned b0r = __float_as_uint(Ws[k8 + t4][nw + nf * 8 + g]);
                unsigned b1r = __float_as_uint(Ws[k8 + t4 + 4][nw + nf * 8 + g]);
                mma_tf32(c[nf], a0, a1, a2, a3, b0r, b1r);
            }
        }
    }
    {
        int r0 = mw + g, r1 = r0 + 8;
        #pragma unroll
        for (int nf = 0; nf < 4; nf++) {
            int cA = nw + nf * 8 + t4 * 2, cB = cA + 1;
            Ts[r0][cA] = c[nf][0] + bi[cA];
            Ts[r0][cB] = c[nf][1] + bi[cB];
            Ts[r1][cA] = c[nf][2] + bi[cA];
            Ts[r1][cB] = c[nf][3] + bi[cB];
        }
    }

    #pragma unroll 1
    for (int j = 0; j < 4; j++) {
        float (*S)[132] = (j & 1) ? Rs : Ts;
        const float* W  = Wbp + j * H_ * H_;
        const float* bv = bb + j * H_;
        #pragma unroll
        for (int i = 0; i < 4; i++) c[i][0] = c[i][1] = c[i][2] = c[i][3] = 0.f;

        for (int kc = 0; kc < H_; kc += 32) {
            __syncthreads();
            #pragma unroll
            for (int i = 0; i < 4; i++) {
                int idx = tid + i * 256;
                int r = idx >> 5, c4 = (idx & 31) << 2;
                *reinterpret_cast<float4*>(&Ws[r][c4]) =
                    *reinterpret_cast<const float4*>(&W[(kc + r) * H_ + c4]);
            }
            __syncthreads();
            #pragma unroll
            for (int k8 = 0; k8 < 32; k8 += 8) {
                int k = kc + k8;
                unsigned a0 = f2tf32(fmaxf(S[mw + g][k + t4], 0.f));
                unsigned a1 = f2tf32(fmaxf(S[mw + g + 8][k + t4], 0.f));
                unsigned a2 = f2tf32(fmaxf(S[mw + g][k + t4 + 4], 0.f));
                unsigned a3 = f2tf32(fmaxf(S[mw + g + 8][k + t4 + 4], 0.f));
                #pragma unroll
                for (int nf = 0; nf < 4; nf++) {
                    unsigned b0r = __float_as_uint(Ws[k8 + t4][nw + nf * 8 + g]);
                    unsigned b1r = __float_as_uint(Ws[k8 + t4 + 4][nw + nf * 8 + g]);
                    mma_tf32(c[nf], a0, a1, a2, a3, b0r, b1r);
                }
            }
        }
        {
            int r0 = mw + g, r1 = r0 + 8;
            #pragma unroll
            for (int nf = 0; nf < 4; nf++) {
                int cA = nw + nf * 8 + t4 * 2, cB = cA + 1;
                if (j & 1) {
                    Ts[r0][cA] += c[nf][0] + bv[cA];
                    Ts[r0][cB] += c[nf][1] + bv[cB];
                    Ts[r1][cA] += c[nf][2] + bv[cA];
                    Ts[r1][cB] += c[nf][3] + bv[cB];
                } else {
                    Rs[r0][cA] = c[nf][0] + bv[cA];
                    Rs[r0][cB] = c[nf][1] + bv[cB];
                    Rs[r1][cA] = c[nf][2] + bv[cA];
                    Rs[r1][cB] = c[nf][3] + bv[cB];
                }
            }
        }
    }
    __syncthreads();
    #pragma unroll
    for (int i = 0; i < 4; i++) {
        int idx = tid + i * 256;
        int r = idx >> 5, c4 = (idx & 31) << 2;
        *reinterpret_cast<float4*>(&tout[(m0 + r) * H_ + c4]) =
            *reinterpret_cast<const float4*>(&Ts[r][c4]);
    }
}

// ---------------- tf32 TC fused Wo GEMM + spline, double-buffered (K16) ------
// Stages: As[2][64][20] + Bs[2][16][200] = 35840 B; Cs(64x200)=51200 B aliases.
__global__ void __launch_bounds__(256)
wo_spline_tc(const float* __restrict__ tmat, const float* __restrict__ Wop,
             const float* __restrict__ bo, const float* __restrict__ zn,
             float* __restrict__ zout, float* __restrict__ lq)
{
    extern __shared__ float sm[];
    float (*As)[64][20]  = reinterpret_cast<float(*)[64][20]>(sm);                 // 2x64x20
    float (*Bs)[16][200] = reinterpret_cast<float(*)[16][200]>(sm + 2 * 64 * 20);  // 2x16x200
    float (*Cs)[200]     = reinterpret_cast<float(*)[200]>(sm);                    // aliases
    __shared__ float bos[192];

    int tid  = threadIdx.x;
    int warp = tid >> 5, lane = tid & 31;
    int mw = (warp & 3) * 16;
    int nw = (warp >> 2) * 96;
    int b0 = blockIdx.y * 64;
    int f0 = blockIdx.x * 8;
    int n0 = blockIdx.x * 192;

    for (int i = tid; i < 192; i += 256) {
        int ff = i / 24, oo = i % 24;
        int col = (f0 + ff) * 23 + oo;
        bos[i] = (oo < 23 && col < OUT_) ? bo[col] : 0.f;
    }

    float c[12][4];
    #pragma unroll
    for (int i = 0; i < 12; i++) { c[i][0] = c[i][1] = c[i][2] = c[i][3] = 0.f; }

    int g = lane >> 2, t4 = lane & 3;

    // fetch indices: A 64x16 = 256 f4 (1/thread); B 16x200(48 f4/row used) = 768 f4 (3/thread)
    int ar = tid >> 2, ac = (tid & 3) << 2;
    int br[3], bc[3];
    #pragma unroll
    for (int i = 0; i < 3; i++) {
        int idx = tid + i * 256;
        br[i] = idx / 48; bc[i] = (idx % 48) << 2;
    }

    float4 sA, sB[3];
    auto fetch = [&](int kc) {
        sA = *reinterpret_cast<const float4*>(&tmat[(b0 + ar) * H_ + kc + ac]);
        #pragma unroll
        for (int i = 0; i < 3; i++)
            sB[i] = *reinterpret_cast<const float4*>(&Wop[(kc + br[i]) * LDW + n0 + bc[i]]);
    };
    auto store = [&](int buf) {
        As[buf][ar][ac + 0] = roundtf(sA.x);
        As[buf][ar][ac + 1] = roundtf(sA.y);
        As[buf][ar][ac + 2] = roundtf(sA.z);
        As[buf][ar][ac + 3] = roundtf(sA.w);
        #pragma unroll
        for (int i = 0; i < 3; i++)
            *reinterpret_cast<float4*>(&Bs[buf][br[i]][bc[i]]) = sB[i];
    };

    fetch(0);
    store(0);
    __syncthreads();

    #pragma unroll 1
    for (int it = 0; it < 8; it++) {
        int buf = it & 1;
        if (it + 1 < 8) fetch((it + 1) * 16);
        #pragma unroll
        for (int k8 = 0; k8 < 16; k8 += 8) {
            unsigned a0 = __float_as_uint(As[buf][mw + g][k8 + t4]);
            unsigned a1 = __float_as_uint(As[buf][mw + g + 8][k8 + t4]);
            unsigned a2 = __float_as_uint(As[buf][mw + g][k8 + t4 + 4]);
            unsigned a3 = __float_as_uint(As[buf][mw + g + 8][k8 + t4 + 4]);
            #pragma unroll
            for (int nt = 0; nt < 12; nt++) {
                unsigned b0r = __float_as_uint(Bs[buf][k8 + t4][nw + nt * 8 + g]);
                unsigned b1r = __float_as_uint(Bs[buf][k8 + t4 + 4][nw + nt * 8 + g]);
                mma_tf32(c[nt], a0, a1, a2, a3, b0r, b1r);
            }
        }
        if (it + 1 < 8) store(buf ^ 1);
        __syncthreads();
    }

    // Store C frags with per-feature 25-stride remap (aliases stage buffers)
    {
        int t2 = (lane & 3) * 2;
        int r0 = mw + g, r1 = r0 + 8;
        #pragma unroll
        for (int nt = 0; nt < 12; nt++) {
            int col0 = nw + nt * 8 + t2;
            int fa = col0 / 24, oa = col0 % 24;
            Cs[r0][fa * 25 + oa] = c[nt][0];
            Cs[r1][fa * 25 + oa] = c[nt][2];
            int col1 = col0 + 1;
            int fb = col1 / 24, ob = col1 % 24;
            Cs[r0][fb * 25 + ob] = c[nt][1];
            Cs[r1][fb * 25 + ob] = c[nt][3];
        }
    }
    __syncthreads();

    int f_local = tid & 7;
    int b_local = tid >> 3;
    int f = f0 + f_local;
    const float scale = 0.08838834764831845f;
    float ld0 = 0.f, ld1 = 0.f;

    if (f < F_) {
        const float* Bo = bos + f_local * 24;
        {
            const float* P = Cs[b_local] + f_local * 25;
            float uw[8], uh[8], ud7[7];
            #pragma unroll
            for (int o = 0; o < 8; o++) {
                uw[o] = (P[o] + Bo[o]) * scale;
                uh[o] = (P[8 + o] + Bo[8 + o]) * scale;
            }
            #pragma unroll
            for (int o = 0; o < 7; o++) ud7[o] = P[16 + o] + Bo[16 + o];
            int b = b0 + b_local;
            float x = zn[b * LDP + 2 * f + 1];
            float o, l;
            rqs_fast(x, uw, uh, ud7, o, l);
            zout[b * LDP + 2 * f + 1] = o;
            ld0 = l;
        }
        {
            const float* P = Cs[b_local + 32] + f_local * 25;
            float uw[8], uh[8], ud7[7];
            #pragma unroll
            for (int o = 0; o < 8; o++) {
                uw[o] = (P[o] + Bo[o]) * scale;
                uh[o] = (P[8 + o] + Bo[8 + o]) * scale;
            }
            #pragma unroll
            for (int o = 0; o < 7; o++) ud7[o] = P[16 + o] + Bo[16 + o];
            int b = b0 + b_local + 32;
            float x = zn[b * LDP + 2 * f + 1];
            float o, l;
            rqs_fast(x, uw, uh, ud7, o, l);
            zout[b * LDP + 2 * f + 1] = o;
            ld1 = l;
        }
    }
    #pragma unroll
    for (int o = 4; o > 0; o >>= 1) {
        ld0 += __shfl_xor_sync(0xffffffffu, ld0, o);
        ld1 += __shfl_xor_sync(0xffffffffu, ld1, o);
    }
    if (f_local == 0) {
        atomicAdd(&lq[b0 + b_local], ld0);
        atomicAdd(&lq[b0 + b_local + 32], ld1);
    }
}

__global__ void final_kernel(const float* __restrict__ z, const float* __restrict__ loc,
                             const float* __restrict__ lsc, const float* __restrict__ lq,
                             const float* __restrict__ slog, float* __restrict__ out)
{
    int b = blockIdx.x;
    float s = 0.f;
    for (int d = threadIdx.x; d < D_; d += blockDim.x) {
        float inv = __expf(-lsc[d]);
        float u = (z[b * LDP + d] - loc[d]) * inv;
        s += lsc[d] + 0.5f * u * u;
    }
    s = block_reduce_sum(s);
    if (threadIdx.x == 0) {
        const float c = 0.5f * 550.f * 1.8378770664093453f;
        out[b] = lq[b] + slog[0] + slog[1] + slog[2] - c - s;
    }
}

// ---------------- launch ----------------
extern "C" void kernel_launch(void* const* d_in, const int* in_sizes, int n_in,
                              void* d_out, int out_size)
{
    (void)in_sizes; (void)n_in; (void)out_size;
    const float* x      = (const float*)d_in[0];
    const float* loc    = (const float*)d_in[1];
    const float* lsc    = (const float*)d_in[2];
    const float* Wi     = (const float*)d_in[3];
    const float* bi     = (const float*)d_in[4];
    const float* Wb     = (const float*)d_in[5];
    const float* bb     = (const float*)d_in[6];
    const float* Wo     = (const float*)d_in[7];
    const float* bo     = (const float*)d_in[8];
    const float* uw_u   = (const float*)d_in[9];
    const float* uh_u   = (const float*)d_in[10];
    const float* ud_u   = (const float*)d_in[11];
    const float* lower  = (const float*)d_in[12];
    const float* upper  = (const float*)d_in[13];
    const float* lu_ud  = (const float*)d_in[14];
    const float* lu_b   = (const float*)d_in[15];
    const int*   perms  = (const int*)d_in[16];
    float* outp = (float*)d_out;

    float *z, *zn, *LT, *UpT, *ApT, *ident, *t, *lq, *slog, *kn, *wop, *wip, *wbp;
    cudaGetSymbolAddress((void**)&z,     g_z);
    cudaGetSymbolAddress((void**)&zn,    g_zn);
    cudaGetSymbolAddress((void**)&LT,    g_LT);
    cudaGetSymbolAddress((void**)&UpT,   g_UpT);
    cudaGetSymbolAddress((void**)&ApT,   g_ApT);
    cudaGetSymbolAddress((void**)&ident, g_id);
    cudaGetSymbolAddress((void**)&t,     g_t);
    cudaGetSymbolAddress((void**)&lq,    g_lq);
    cudaGetSymbolAddress((void**)&slog,  g_slog);
    cudaGetSymbolAddress((void**)&kn,    g_kn);
    cudaGetSymbolAddress((void**)&wop,   g_Wop);
    cudaGetSymbolAddress((void**)&wip,   g_Wip);
    cudaGetSymbolAddress((void**)&wbp,   g_Wbp);

    constexpr int RESNET_SMEM = (64 * 132 + 32 * 136 + 32 * 36) * 4;  // 55808 B
    constexpr int WOSP_SMEM   = 64 * 200 * 4;                          // 51200 B (Cs floor)
    constexpr int PREP_TOTAL = 288 * H_ + 4 * H_ * H_ + H_ * LDW;
    static bool attr_set = false;
    if (!attr_set) {
        cudaFuncSetAttribute(wo_spline_tc,
                             cudaFuncAttributeMaxDynamicSharedMemorySize, WOSP_SMEM);
        cudaFuncSetAttribute(resnet_fused,
                             cudaFuncAttributeMaxDynamicSharedMemorySize, RESNET_SMEM);
        attr_set = true;
    }

    auto big_gemm = [&](const float* src, const float* bias) {
        lu_gemm_tc<<<dim3((D_ + 63) / 64, B_ / 128), 256>>>(src, ApT, bias, zn);
    };
    auto apt_gemm = [&]() {
        apt_gemm_tc<<<dim3((D_ + 63) / 64, (D_ + 127) / 128), 256>>>(UpT, LT, ApT);
    };

    auto resnet_and_tail = [&](int i) {
        ident_knots_kernel<<<(F_ + 255) / 256, 256>>>(
            uw_u + i * F_ * 8, uh_u + i * F_ * 8, ud_u + i * F_ * 7, kn);
        ident_eval_kernel<<<dim3((F_ + 31) / 32, B_ / 8), 256>>>(
            zn, kn, ident, z, lq);
        prep_weights_kernel<<<(PREP_TOTAL + 255) / 256, 256>>>(
            Wi + i * F_ * H_, Wb + i * 4 * H_ * H_, Wo + i * H_ * OUT_,
            wip, wbp, wop);
        resnet_fused<<<B_ / 32, 256, RESNET_SMEM>>>(
            ident, wip, bi + i * H_, wbp, bb + i * 4 * H_, t);
        wo_spline_tc<<<dim3((F_ + 7) / 8, B_ / 64), 256, WOSP_SMEM>>>(
            t, wop, bo + i * OUT_, zn, z, lq);
    };

    // ---- layer 2 prelude, ordered so the TC BIG GEMM is launch index 3 (ncu) ----
    build_lt_upt_kernel<<<dim3((D_ + 255) / 256, D_, 2), 256>>>(          // 0
        lower + 2 * D_ * D_, upper + 2 * D_ * D_, lu_ud + 2 * D_, perms + 2 * D_, LT, UpT);
    apt_gemm();                                                            // 1
    copy_pad_kernel<<<(B_ * D_ + 255) / 256, 256>>>(x, z);                 // 2
    big_gemm(z, lu_b + 2 * D_);                                            // 3 <- profiled
    zero_kernel<<<(B_ + 255) / 256, 256>>>(lq, B_);                        // 4
    sumlog_kernel<<<3, 256>>>(lu_ud, slog);                                // 5
    resnet_and_tail(2);

    for (int i = 1; i >= 0; i--) {
        build_lt_upt_kernel<<<dim3((D_ + 255) / 256, D_, 2), 256>>>(
            lower + i * D_ * D_, upper + i * D_ * D_,
            lu_ud + i * D_, perms + i * D_, LT, UpT);
        apt_gemm();
        big_gemm(z, lu_b + i * D_);
        resnet_and_tail(i);
    }

    final_kernel<<<B_, 256>>>(z, loc, lsc, lq, slog, outp);
}

// round 16
// speedup vs baseline: 1.0654x; 1.0654x over previous
#include <cuda_runtime.h>
#include <math.h>

// ---------------- problem constants ----------------
namespace {
constexpr int D_   = 550;
constexpr int LDP  = 560;    // padded lead dim: 35*16, all pads guaranteed zero
constexpr int MATR = 640;    // matrix buffer rows (128-tile coverage, zero pads)
constexpr int F_   = 275;
constexpr int LDF  = 288;    // padded ident stride (36*8, zero pads -> guard-free K)
constexpr int B_   = 4096;   // N*T = 8*512
constexpr int H_   = 128;
constexpr int OUT_ = 6325;   // F_*(3*8-1)
constexpr int LDW  = 6720;   // padded Wo cols: 280 features * 24
}

// ---------------- scratch (device globals; no allocs allowed) ----------------
__device__ float g_z  [B_*LDP];     // zero-init => pad cols stay 0
__device__ float g_zn [B_*LDP];
__device__ float g_LT [MATR*LDP];   // side-stream private
__device__ float g_UpT[MATR*LDP];   // side-stream private
__device__ float g_ApT[3][MATR*LDP];// per-layer, tf32-rounded
__device__ float g_id [B_*LDF];     // tf32-rounded; zero-init pads
__device__ float g_t  [B_*H_];
__device__ float g_lq [B_];
__device__ float g_slog[3];
__device__ float g_kn [3][F_*27];   // per-layer ident knots
__device__ float g_Wop[3][H_*LDW];  // per-layer padded Wo, tf32-rounded
__device__ float g_Wip[3][288*H_];  // per-layer padded Wi, tf32-rounded
__device__ float g_Wbp[3][4*H_*H_]; // per-layer Wb, tf32-rounded

// ---------------- helpers ----------------
__device__ __forceinline__ float softplus_acc(float x) {
    return (x > 20.f) ? x : log1pf(__expf(x));
}
__device__ __forceinline__ float softplus_fast(float x) {
    return (x > 15.f) ? x : __logf(1.f + __expf(x));
}

__device__ __forceinline__ unsigned f2tf32(float x) {
    unsigned r; asm("cvt.rna.tf32.f32 %0, %1;" : "=r"(r) : "f"(x)); return r;
}
__device__ __forceinline__ float roundtf(float x) {
    return __uint_as_float(f2tf32(x));
}

__device__ __forceinline__ void mma_tf32(float* c,
    unsigned a0, unsigned a1, unsigned a2, unsigned a3,
    unsigned b0, unsigned b1)
{
    asm volatile(
        "mma.sync.aligned.m16n8k8.row.col.f32.tf32.tf32.f32 "
        "{%0,%1,%2,%3}, {%4,%5,%6,%7}, {%8,%9}, {%0,%1,%2,%3};\n"
        : "+f"(c[0]), "+f"(c[1]), "+f"(c[2]), "+f"(c[3])
        : "r"(a0), "r"(a1), "r"(a2), "r"(a3), "r"(b0), "r"(b1));
}

__device__ __forceinline__ float block_reduce_sum(float v) {
    __shared__ float sred[32];
    int tid = threadIdx.x;
    #pragma unroll
    for (int o = 16; o > 0; o >>= 1) v += __shfl_down_sync(0xffffffffu, v, o);
    if ((tid & 31) == 0) sred[tid >> 5] = v;
    __syncthreads();
    if (tid < 32) {
        int nw = (blockDim.x + 31) >> 5;
        v = (tid < nw) ? sred[tid] : 0.f;
        #pragma unroll
        for (int o = 16; o > 0; o >>= 1) v += __shfl_down_sync(0xffffffffu, v, o);
    }
    return v;
}

// Fast inverse RQS, params in registers (conditional path).
__device__ __forceinline__ void rqs_fast(float x, const float* uw, const float* uh,
                                         const float* ud7, float& out, float& ld)
{
    const float TB = 3.f;
    bool inside = (x >= -TB) && (x <= TB);
    float xi = fminf(fmaxf(x, -TB), TB);

    float cw[9], ch[9];
    {
        float m = uw[0];
        #pragma unroll
        for (int k = 1; k < 8; k++) m = fmaxf(m, uw[k]);
        float e[8]; float s = 0.f;
        #pragma unroll
        for (int k = 0; k < 8; k++) { e[k] = __expf(uw[k] - m); s += e[k]; }
        float inv = __fdividef(1.f, s);
        float cum = 0.f;
        cw[0] = -TB;
        #pragma unroll
        for (int k = 0; k < 7; k++) { cum += 0.001f + 0.992f * e[k] * inv; cw[k+1] = 6.f * cum - 3.f; }
        cw[8] = TB;
    }
    {
        float m = uh[0];
        #pragma unroll
        for (int k = 1; k < 8; k++) m = fmaxf(m, uh[k]);
        float e[8]; float s = 0.f;
        #pragma unroll
        for (int k = 0; k < 8; k++) { e[k] = __expf(uh[k] - m); s += e[k]; }
        float inv = __fdividef(1.f, s);
        float cum = 0.f;
        ch[0] = -TB;
        #pragma unroll
        for (int k = 0; k < 7; k++) { cum += 0.001f + 0.992f * e[k] * inv; ch[k+1] = 6.f * cum - 3.f; }
        ch[8] = TB;
    }

    int cnt = 0;
    #pragma unroll
    for (int k = 0; k < 9; k++) {
        float lo = ch[k] + (k == 8 ? 1e-6f : 0.f);
        cnt += (xi >= lo) ? 1 : 0;
    }
    int idx = cnt - 1; idx = idx < 0 ? 0 : (idx > 7 ? 7 : idx);

    float icw = 0.f, iw = 1.f, ich = 0.f, ih = 1.f;
    float u0 = 0.f, u1 = 0.f;
    #pragma unroll
    for (int k = 0; k < 8; k++) {
        if (k == idx) {
            icw = cw[k]; iw = cw[k+1] - cw[k];
            ich = ch[k]; ih = ch[k+1] - ch[k];
        }
    }
    #pragma unroll
    for (int k = 0; k < 7; k++) {
        if (k == idx - 1) u0 = ud7[k];
        if (k == idx)     u1 = ud7[k];
    }
    float d0 = (idx == 0) ? 1.f : 0.001f + softplus_fast(u0);
    float d1 = (idx == 7) ? 1.f : 0.001f + softplus_fast(u1);

    float delta = __fdividef(ih, iw);
    float t  = xi - ich;
    float s2 = d0 + d1 - 2.f * delta;
    float aa = t * s2 + ih * (delta - d0);
    float bb = ih * d0 - t * s2;
    float cc = -delta * t;
    float disc = bb * bb - 4.f * aa * cc;
    float sq = disc * __frsqrt_rn(fmaxf(disc, 1e-37f));
    float root = __fdividef(2.f * cc, -bb - sq);
    float o = root * iw + icw;
    float tm = root * (1.f - root);
    float den = delta + s2 * tm;
    float omr = 1.f - root;
    float dnum = delta * delta * (d1 * root * root + 2.f * delta * tm + d0 * omr * omr);
    float l = -__logf(__fdividef(dnum, den * den));

    out = inside ? o : x;
    ld  = inside ? l : 0.f;
}

// ---------------- small kernels ----------------
__global__ void zero_kernel(float* p, int n) {
    int i = blockIdx.x * blockDim.x + threadIdx.x;
    if (i < n) p[i] = 0.f;
}

__global__ void copy_pad_kernel(const float* __restrict__ x, float* __restrict__ z) {
    int i = blockIdx.x * blockDim.x + threadIdx.x;
    if (i >= B_ * D_) return;
    int b = i / D_, d = i % D_;
    z[b * LDP + d] = x[i];
}

__global__ void sumlog_kernel(const float* __restrict__ lu_ud, float* __restrict__ out) {
    int i = blockIdx.x;
    float s = 0.f;
    for (int d = threadIdx.x; d < D_; d += blockDim.x)
        s += __logf(softplus_acc(lu_ud[i * D_ + d]) + 0.001f);
    s = block_reduce_sum(s);
    if (threadIdx.x == 0) out[i] = s;
}

// Combined per-layer weight prep (tf32-rounded at materialization).
__global__ void prep_weights_kernel(const float* __restrict__ Wi,
                                    const float* __restrict__ Wb,
                                    const float* __restrict__ Wo,
                                    float* __restrict__ Wip,
                                    float* __restrict__ Wbp,
                                    float* __restrict__ Wop)
{
    constexpr int N_WIP = 288 * H_;
    constexpr int N_WBP = 4 * H_ * H_;
    constexpr int N_WOP = H_ * LDW;
    int idx = blockIdx.x * blockDim.x + threadIdx.x;
    if (idx < N_WIP) {
        int f = idx / H_, h = idx % H_;
        Wip[idx] = (f < F_) ? roundtf(Wi[f * H_ + h]) : 0.f;
    } else if (idx < N_WIP + N_WBP) {
        int j = idx - N_WIP;
        Wbp[j] = roundtf(Wb[j]);
    } else if (idx < N_WIP + N_WBP + N_WOP) {
        int j = idx - N_WIP - N_WBP;
        int k = j / LDW, c = j % LDW;
        int f = c / 24, o = c % 24;
        float v = 0.f;
        if (o < 23 && f < F_) v = roundtf(Wo[k * OUT_ + f * 23 + o]);
        Wop[j] = v;
    }
}

// Per-f knots for the unconditional (ident) spline
__global__ void ident_knots_kernel(const float* __restrict__ uw_u,
                                   const float* __restrict__ uh_u,
                                   const float* __restrict__ ud_u,
                                   float* __restrict__ kn)
{
    int f = blockIdx.x * blockDim.x + threadIdx.x;
    if (f >= F_) return;
    const float TB = 3.f;
    float* o = kn + f * 27;
    {
        const float* u = uw_u + f * 8;
        float m = u[0];
        #pragma unroll
        for (int k = 1; k < 8; k++) m = fmaxf(m, u[k]);
        float e[8]; float s = 0.f;
        #pragma unroll
        for (int k = 0; k < 8; k++) { e[k] = __expf(u[k] - m); s += e[k]; }
        float inv = 1.f / s;
        float cum = 0.f;
        o[0] = -TB;
        #pragma unroll
        for (int k = 0; k < 7; k++) { cum += 0.001f + 0.992f * e[k] * inv; o[k+1] = 6.f * cum - 3.f; }
        o[8] = TB;
    }
    {
        const float* u = uh_u + f * 8;
        float m = u[0];
        #pragma unroll
        for (int k = 1; k < 8; k++) m = fmaxf(m, u[k]);
        float e[8]; float s = 0.f;
        #pragma unroll
        for (int k = 0; k < 8; k++) { e[k] = __expf(u[k] - m); s += e[k]; }
        float inv = 1.f / s;
        float cum = 0.f;
        o[9] = -TB;
        #pragma unroll
        for (int k = 0; k < 7; k++) { cum += 0.001f + 0.992f * e[k] * inv; o[10+k] = 6.f * cum - 3.f; }
        o[17] = TB;
    }
    o[18] = 1.f; o[26] = 1.f;
    #pragma unroll
    for (int k = 0; k < 7; k++) o[19 + k] = 0.001f + softplus_acc(ud_u[f * 7 + k]);
}

// Table-driven ident spline eval. Block = 32 f x 8 b (256 thr).
__global__ void __launch_bounds__(256)
ident_eval_kernel(const float* __restrict__ zn, const float* __restrict__ kn,
                  float* __restrict__ ident, float* __restrict__ zout,
                  float* __restrict__ lq)
{
    __shared__ float sk[32][29];
    int tid = threadIdx.x;
    int f_local = tid & 31;
    int b_local = tid >> 5;
    int f0 = blockIdx.x * 32;
    int b  = blockIdx.y * 8 + b_local;

    for (int j = tid; j < 32 * 27; j += 256) {
        int fl = j / 27, e = j % 27;
        int f = f0 + fl;
        sk[fl][e] = (f < F_) ? kn[f * 27 + e] : 0.f;
    }
    __syncthreads();

    int f = f0 + f_local;
    float ldv = 0.f;
    if (f < F_) {
        const float TB = 3.f;
        const float* K = sk[f_local];
        float x = zn[b * LDP + 2 * f];
        bool inside = (x >= -TB) && (x <= TB);
        float xi = fminf(fmaxf(x, -TB), TB);

        int cnt = 0;
        #pragma unroll
        for (int k = 0; k < 9; k++) {
            float lo = K[9 + k] + (k == 8 ? 1e-6f : 0.f);
            cnt += (xi >= lo) ? 1 : 0;
        }
        int idx = cnt - 1; idx = idx < 0 ? 0 : (idx > 7 ? 7 : idx);

        float icw = K[idx],     iw = K[idx + 1] - icw;
        float ich = K[9 + idx], ih = K[10 + idx] - ich;
        float d0  = K[18 + idx], d1 = K[19 + idx];

        float delta = __fdividef(ih, iw);
        float t  = xi - ich;
        float s2 = d0 + d1 - 2.f * delta;
        float aa = t * s2 + ih * (delta - d0);
        float bb = ih * d0 - t * s2;
        float cc = -delta * t;
        float disc = bb * bb - 4.f * aa * cc;
        float sq = disc * __frsqrt_rn(fmaxf(disc, 1e-37f));
        float root = __fdividef(2.f * cc, -bb - sq);
        float o = root * iw + icw;
        float tm = root * (1.f - root);
        float den = delta + s2 * tm;
        float omr = 1.f - root;
        float dnum = delta * delta * (d1 * root * root + 2.f * delta * tm + d0 * omr * omr);
        float l = -__logf(__fdividef(dnum, den * den));

        float ov = inside ? o : x;
        ldv = inside ? l : 0.f;
        ident[b * LDF + f] = roundtf(ov);
        zout[b * LDP + 2 * f] = ov;
    }
    #pragma unroll
    for (int o = 16; o > 0; o >>= 1) ldv += __shfl_xor_sync(0xffffffffu, ldv, o);
    if (f_local == 0) atomicAdd(&lq[b], ldv);
}

// Materialize LT[m,d] = L[d,m] (unit diag) and UpT[perm[k], m] = Udense[m,k].
__global__ void build_lt_upt_kernel(const float* __restrict__ lower,
                                    const float* __restrict__ upper,
                                    const float* __restrict__ lu_ud,
                                    const int* __restrict__ perm,
                                    float* __restrict__ LT, float* __restrict__ UpT)
{
    int c = blockIdx.x * blockDim.x + threadIdx.x;
    int rr = blockIdx.y;
    if (c >= D_) return;
    if (blockIdx.z == 0) {
        int m = rr, d = c;
        float v = (m < d) ? lower[d * D_ + m] : ((m == d) ? 1.f : 0.f);
        LT[m * LDP + d] = v;
    } else {
        int k = rr, m = c;
        float v;
        if (m < k)       v = upper[m * D_ + k];
        else if (m == k) v = softplus_acc(lu_ud[k]) + 0.001f;
        else             v = 0.f;
        UpT[perm[k] * LDP + m] = v;
    }
}

// ---------------- tf32 TC GEMM core (128m x 64n, double-buffered) ------------
template<bool RND_B, bool HASB, bool TFOUT>
__device__ __forceinline__ void tc_gemm_128x64(
    const float* __restrict__ A, int lda,
    const float* __restrict__ Bm, int ldb,
    const float* __restrict__ bias, float* __restrict__ C, int ldc,
    int m0, int n0, int K, int Nvalid,
    float (*As)[128][20], float (*Bs)[16][72])
{
    int tid  = threadIdx.x;
    int warp = tid >> 5, lane = tid & 31;
    int mwarp = (warp & 3) * 32;
    int nwarp = (warp >> 2) * 32;
    int g = lane >> 2, t4 = lane & 3;

    int arow0 = tid >> 2,            acol = (tid & 3) << 2;
    int arow1 = (tid + 256) >> 2;
    int brow  = tid >> 4,            bcol = (tid & 15) << 2;

    float c[2][4][4];
    #pragma unroll
    for (int i = 0; i < 2; i++)
        #pragma unroll
        for (int j = 0; j < 4; j++)
            c[i][j][0] = c[i][j][1] = c[i][j][2] = c[i][j][3] = 0.f;

    float4 sA0, sA1, sB;
    auto fetch = [&](int kc) {
        sA0 = *reinterpret_cast<const float4*>(&A[(m0 + arow0) * lda + kc + acol]);
        sA1 = *reinterpret_cast<const float4*>(&A[(m0 + arow1) * lda + kc + acol]);
        sB  = *reinterpret_cast<const float4*>(&Bm[(kc + brow) * ldb + n0 + bcol]);
    };
    auto store = [&](int buf) {
        float4 v = sA0;
        v.x = roundtf(v.x); v.y = roundtf(v.y); v.z = roundtf(v.z); v.w = roundtf(v.w);
        *reinterpret_cast<float4*>(&As[buf][arow0][acol]) = v;
        v = sA1;
        v.x = roundtf(v.x); v.y = roundtf(v.y); v.z = roundtf(v.z); v.w = roundtf(v.w);
        *reinterpret_cast<float4*>(&As[buf][arow1][acol]) = v;
        float4 w = sB;
        if (RND_B) {
            w.x = roundtf(w.x); w.y = roundtf(w.y);
            w.z = roundtf(w.z); w.w = roundtf(w.w);
        }
        *reinterpret_cast<float4*>(&Bs[buf][brow][bcol]) = w;
    };

    int NIT = K / 16;
    fetch(0);
    store(0);
    __syncthreads();

    for (int it = 0; it < NIT; it++) {
        int buf = it & 1;
        if (it + 1 < NIT) fetch((it + 1) * 16);
        #pragma unroll
        for (int k8 = 0; k8 < 16; k8 += 8) {
            #pragma unroll
            for (int mf = 0; mf < 2; mf++) {
                int mb = mwarp + mf * 16;
                unsigned a0 = __float_as_uint(As[buf][mb + g][k8 + t4]);
                unsigned a1 = __float_as_uint(As[buf][mb + g + 8][k8 + t4]);
                unsigned a2 = __float_as_uint(As[buf][mb + g][k8 + t4 + 4]);
                unsigned a3 = __float_as_uint(As[buf][mb + g + 8][k8 + t4 + 4]);
                #pragma unroll
                for (int nf = 0; nf < 4; nf++) {
                    unsigned b0r = __float_as_uint(Bs[buf][k8 + t4][nwarp + nf * 8 + g]);
                    unsigned b1r = __float_as_uint(Bs[buf][k8 + t4 + 4][nwarp + nf * 8 + g]);
                    mma_tf32(c[mf][nf], a0, a1, a2, a3, b0r, b1r);
                }
            }
        }
        if (it + 1 < NIT) store(buf ^ 1);
        __syncthreads();
    }

    #pragma unroll
    for (int mf = 0; mf < 2; mf++) {
        int r0 = m0 + mwarp + mf * 16 + g;
        int r1 = r0 + 8;
        #pragma unroll
        for (int nf = 0; nf < 4; nf++) {
            int cA = n0 + nwarp + nf * 8 + t4 * 2;
            int cB = cA + 1;
            if (cA < Nvalid) {
                float v0 = c[mf][nf][0] + (HASB ? bias[cA] : 0.f);
                float v2 = c[mf][nf][2] + (HASB ? bias[cA] : 0.f);
                C[r0 * ldc + cA] = TFOUT ? roundtf(v0) : v0;
                C[r1 * ldc + cA] = TFOUT ? roundtf(v2) : v2;
            }
            if (cB < Nvalid) {
                float v1 = c[mf][nf][1] + (HASB ? bias[cB] : 0.f);
                float v3 = c[mf][nf][3] + (HASB ? bias[cB] : 0.f);
                C[r0 * ldc + cB] = TFOUT ? roundtf(v1) : v1;
                C[r1 * ldc + cB] = TFOUT ? roundtf(v3) : v3;
            }
        }
    }
}

// zn = src @ ApT + bias (ApT pre-rounded)
__global__ void __launch_bounds__(256)
lu_gemm_tc(const float* __restrict__ src, const float* __restrict__ ApT,
           const float* __restrict__ bias, float* __restrict__ C)
{
    __shared__ __align__(16) float As[2][128][20];
    __shared__ __align__(16) float Bs[2][16][72];
    tc_gemm_128x64<false, true, false>(
        src, LDP, ApT, LDP, bias, C, LDP,
        blockIdx.y * 128, blockIdx.x * 64, LDP, D_, As, Bs);
}

// ApT = UpT @ LT (both fp32, rounded in-loop; output rounded)
__global__ void __launch_bounds__(256)
apt_gemm_tc(const float* __restrict__ UpT, const float* __restrict__ LT,
            float* __restrict__ ApT)
{
    __shared__ __align__(16) float As[2][128][20];
    __shared__ __align__(16) float Bs[2][16][72];
    tc_gemm_128x64<true, false, true>(
        UpT, LDP, LT, LDP, nullptr, ApT, LDP,
        blockIdx.y * 128, blockIdx.x * 64, LDP, D_, As, Bs);
}

// ---------------- fused tf32 resnet: t = resnet(ident) per 32-row block ------
__global__ void __launch_bounds__(256)
resnet_fused(const float* __restrict__ ident, const float* __restrict__ Wip,
             const float* __restrict__ bi, const float* __restrict__ Wbp,
             const float* __restrict__ bb, float* __restrict__ tout)
{
    extern __shared__ float smf[];
    float (*Ts)[132] = reinterpret_cast<float(*)[132]>(smf);
    float (*Rs)[132] = reinterpret_cast<float(*)[132]>(smf + 32 * 132);
    float (*Ws)[136] = reinterpret_cast<float(*)[136]>(smf + 64 * 132);
    float (*As)[36]  = reinterpret_cast<float(*)[36]>(smf + 64 * 132 + 32 * 136);

    int tid = threadIdx.x, warp = tid >> 5, lane = tid & 31;
    int mw = (warp & 1) * 16;
    int nw = (warp >> 1) * 32;
    int m0 = blockIdx.x * 32;
    int g = lane >> 2, t4 = lane & 3;

    float c[4][4];

    #pragma unroll
    for (int i = 0; i < 4; i++) c[i][0] = c[i][1] = c[i][2] = c[i][3] = 0.f;

    for (int kc = 0; kc < 288; kc += 32) {
        __syncthreads();
        {
            int r = tid >> 3, c4 = (tid & 7) << 2;
            *reinterpret_cast<float4*>(&As[r][c4]) =
                *reinterpret_cast<const float4*>(&ident[(m0 + r) * LDF + kc + c4]);
        }
        #pragma unroll
        for (int i = 0; i < 4; i++) {
            int idx = tid + i * 256;
            int r = idx >> 5, c4 = (idx & 31) << 2;
            *reinterpret_cast<float4*>(&Ws[r][c4]) =
                *reinterpret_cast<const float4*>(&Wip[(kc + r) * H_ + c4]);
        }
        __syncthreads();
        #pragma unroll
        for (int k8 = 0; k8 < 32; k8 += 8) {
            unsigned a0 = __float_as_uint(As[mw + g][k8 + t4]);
            unsigned a1 = __float_as_uint(As[mw + g + 8][k8 + t4]);
            unsigned a2 = __float_as_uint(As[mw + g][k8 + t4 + 4]);
            unsigned a3 = __float_as_uint(As[mw + g + 8][k8 + t4 + 4]);
            #pragma unroll
            for (int nf = 0; nf < 4; nf++) {
                unsigned b0r = __float_as_uint(Ws[k8 + t4][nw + nf * 8 + g]);
                unsigned b1r = __float_as_uint(Ws[k8 + t4 + 4][nw + nf * 8 + g]);
                mma_tf32(c[nf], a0, a1, a2, a3, b0r, b1r);
            }
        }
    }
    {
        int r0 = mw + g, r1 = r0 + 8;
        #pragma unroll
        for (int nf = 0; nf < 4; nf++) {
            int cA = nw + nf * 8 + t4 * 2, cB = cA + 1;
            Ts[r0][cA] = c[nf][0] + bi[cA];
            Ts[r0][cB] = c[nf][1] + bi[cB];
            Ts[r1][cA] = c[nf][2] + bi[cA];
            Ts[r1][cB] = c[nf][3] + bi[cB];
        }
    }

    #pragma unroll 1
    for (int j = 0; j < 4; j++) {
        float (*S)[132] = (j & 1) ? Rs : Ts;
        const float* W  = Wbp + j * H_ * H_;
        const float* bv = bb + j * H_;
        #pragma unroll
        for (int i = 0; i < 4; i++) c[i][0] = c[i][1] = c[i][2] = c[i][3] = 0.f;

        for (int kc = 0; kc < H_; kc += 32) {
            __syncthreads();
            #pragma unroll
            for (int i = 0; i < 4; i++) {
                int idx = tid + i * 256;
                int r = idx >> 5, c4 = (idx & 31) << 2;
                *reinterpret_cast<float4*>(&Ws[r][c4]) =
                    *reinterpret_cast<const float4*>(&W[(kc + r) * H_ + c4]);
            }
            __syncthreads();
            #pragma unroll
            for (int k8 = 0; k8 < 32; k8 += 8) {
                int k = kc + k8;
                unsigned a0 = f2tf32(fmaxf(S[mw + g][k + t4], 0.f));
                unsigned a1 = f2tf32(fmaxf(S[mw + g + 8][k + t4], 0.f));
                unsigned a2 = f2tf32(fmaxf(S[mw + g][k + t4 + 4], 0.f));
                unsigned a3 = f2tf32(fmaxf(S[mw + g + 8][k + t4 + 4], 0.f));
                #pragma unroll
                for (int nf = 0; nf < 4; nf++) {
                    unsigned b0r = __float_as_uint(Ws[k8 + t4][nw + nf * 8 + g]);
                    unsigned b1r = __float_as_uint(Ws[k8 + t4 + 4][nw + nf * 8 + g]);
                    mma_tf32(c[nf], a0, a1, a2, a3, b0r, b1r);
                }
            }
        }
        {
            int r0 = mw + g, r1 = r0 + 8;
            #pragma unroll
            for (int nf = 0; nf < 4; nf++) {
                int cA = nw + nf * 8 + t4 * 2, cB = cA + 1;
                if (j & 1) {
                    Ts[r0][cA] += c[nf][0] + bv[cA];
                    Ts[r0][cB] += c[nf][1] + bv[cB];
                    Ts[r1][cA] += c[nf][2] + bv[cA];
                    Ts[r1][cB] += c[nf][3] + bv[cB];
                } else {
                    Rs[r0][cA] = c[nf][0] + bv[cA];
                    Rs[r0][cB] = c[nf][1] + bv[cB];
                    Rs[r1][cA] = c[nf][2] + bv[cA];
                    Rs[r1][cB] = c[nf][3] + bv[cB];
                }
            }
        }
    }
    __syncthreads();
    #pragma unroll
    for (int i = 0; i < 4; i++) {
        int idx = tid + i * 256;
        int r = idx >> 5, c4 = (idx & 31) << 2;
        *reinterpret_cast<float4*>(&tout[(m0 + r) * H_ + c4]) =
            *reinterpret_cast<const float4*>(&Ts[r][c4]);
    }
}

// ---------------- tf32 TC fused Wo GEMM + spline, double-buffered (K16) ------
__global__ void __launch_bounds__(256)
wo_spline_tc(const float* __restrict__ tmat, const float* __restrict__ Wop,
             const float* __restrict__ bo, const float* __restrict__ zn,
             float* __restrict__ zout, float* __restrict__ lq)
{
    extern __shared__ float sm[];
    float (*As)[64][20]  = reinterpret_cast<float(*)[64][20]>(sm);
    float (*Bs)[16][200] = reinterpret_cast<float(*)[16][200]>(sm + 2 * 64 * 20);
    float (*Cs)[200]     = reinterpret_cast<float(*)[200]>(sm);
    __shared__ float bos[192];

    int tid  = threadIdx.x;
    int warp = tid >> 5, lane = tid & 31;
    int mw = (warp & 3) * 16;
    int nw = (warp >> 2) * 96;
    int b0 = blockIdx.y * 64;
    int f0 = blockIdx.x * 8;
    int n0 = blockIdx.x * 192;

    for (int i = tid; i < 192; i += 256) {
        int ff = i / 24, oo = i % 24;
        int col = (f0 + ff) * 23 + oo;
        bos[i] = (oo < 23 && col < OUT_) ? bo[col] : 0.f;
    }

    float c[12][4];
    #pragma unroll
    for (int i = 0; i < 12; i++) { c[i][0] = c[i][1] = c[i][2] = c[i][3] = 0.f; }

    int g = lane >> 2, t4 = lane & 3;

    int ar = tid >> 2, ac = (tid & 3) << 2;
    int br[3], bc[3];
    #pragma unroll
    for (int i = 0; i < 3; i++) {
        int idx = tid + i * 256;
        br[i] = idx / 48; bc[i] = (idx % 48) << 2;
    }

    float4 sA, sB[3];
    auto fetch = [&](int kc) {
        sA = *reinterpret_cast<const float4*>(&tmat[(b0 + ar) * H_ + kc + ac]);
        #pragma unroll
        for (int i = 0; i < 3; i++)
            sB[i] = *reinterpret_cast<const float4*>(&Wop[(kc + br[i]) * LDW + n0 + bc[i]]);
    };
    auto store = [&](int buf) {
        As[buf][ar][ac + 0] = roundtf(sA.x);
        As[buf][ar][ac + 1] = roundtf(sA.y);
        As[buf][ar][ac + 2] = roundtf(sA.z);
        As[buf][ar][ac + 3] = roundtf(sA.w);
        #pragma unroll
        for (int i = 0; i < 3; i++)
            *reinterpret_cast<float4*>(&Bs[buf][br[i]][bc[i]]) = sB[i];
    };

    fetch(0);
    store(0);
    __syncthreads();

    #pragma unroll 1
    for (int it = 0; it < 8; it++) {
        int buf = it & 1;
        if (it + 1 < 8) fetch((it + 1) * 16);
        #pragma unroll
        for (int k8 = 0; k8 < 16; k8 += 8) {
            unsigned a0 = __float_as_uint(As[buf][mw + g][k8 + t4]);
            unsigned a1 = __float_as_uint(As[buf][mw + g + 8][k8 + t4]);
            unsigned a2 = __float_as_uint(As[buf][mw + g][k8 + t4 + 4]);
            unsigned a3 = __float_as_uint(As[buf][mw + g + 8][k8 + t4 + 4]);
            #pragma unroll
            for (int nt = 0; nt < 12; nt++) {
                unsigned b0r = __float_as_uint(Bs[buf][k8 + t4][nw + nt * 8 + g]);
                unsigned b1r = __float_as_uint(Bs[buf][k8 + t4 + 4][nw + nt * 8 + g]);
                mma_tf32(c[nt], a0, a1, a2, a3, b0r, b1r);
            }
        }
        if (it + 1 < 8) store(buf ^ 1);
        __syncthreads();
    }

    {
        int t2 = (lane & 3) * 2;
        int r0 = mw + g, r1 = r0 + 8;
        #pragma unroll
        for (int nt = 0; nt < 12; nt++) {
            int col0 = nw + nt * 8 + t2;
            int fa = col0 / 24, oa = col0 % 24;
            Cs[r0][fa * 25 + oa] = c[nt][0];
            Cs[r1][fa * 25 + oa] = c[nt][2];
            int col1 = col0 + 1;
            int fb = col1 / 24, ob = col1 % 24;
            Cs[r0][fb * 25 + ob] = c[nt][1];
            Cs[r1][fb * 25 + ob] = c[nt][3];
        }
    }
    __syncthreads();

    int f_local = tid & 7;
    int b_local = tid >> 3;
    int f = f0 + f_local;
    const float scale = 0.08838834764831845f;
    float ld0 = 0.f, ld1 = 0.f;

    if (f < F_) {
        const float* Bo = bos + f_local * 24;
        {
            const float* P = Cs[b_local] + f_local * 25;
            float uw[8], uh[8], ud7[7];
            #pragma unroll
            for (int o = 0; o < 8; o++) {
                uw[o] = (P[o] + Bo[o]) * scale;
                uh[o] = (P[8 + o] + Bo[8 + o]) * scale;
            }
            #pragma unroll
            for (int o = 0; o < 7; o++) ud7[o] = P[16 + o] + Bo[16 + o];
            int b = b0 + b_local;
            float x = zn[b * LDP + 2 * f + 1];
            float o, l;
            rqs_fast(x, uw, uh, ud7, o, l);
            zout[b * LDP + 2 * f + 1] = o;
            ld0 = l;
        }
        {
            const float* P = Cs[b_local + 32] + f_local * 25;
            float uw[8], uh[8], ud7[7];
            #pragma unroll
            for (int o = 0; o < 8; o++) {
                uw[o] = (P[o] + Bo[o]) * scale;
                uh[o] = (P[8 + o] + Bo[8 + o]) * scale;
            }
            #pragma unroll
            for (int o = 0; o < 7; o++) ud7[o] = P[16 + o] + Bo[16 + o];
            int b = b0 + b_local + 32;
            float x = zn[b * LDP + 2 * f + 1];
            float o, l;
            rqs_fast(x, uw, uh, ud7, o, l);
            zout[b * LDP + 2 * f + 1] = o;
            ld1 = l;
        }
    }
    #pragma unroll
    for (int o = 4; o > 0; o >>= 1) {
        ld0 += __shfl_xor_sync(0xffffffffu, ld0, o);
        ld1 += __shfl_xor_sync(0xffffffffu, ld1, o);
    }
    if (f_local == 0) {
        atomicAdd(&lq[b0 + b_local], ld0);
        atomicAdd(&lq[b0 + b_local + 32], ld1);
    }
}

__global__ void final_kernel(const float* __restrict__ z, const float* __restrict__ loc,
                             const float* __restrict__ lsc, const float* __restrict__ lq,
                             const float* __restrict__ slog, float* __restrict__ out)
{
    int b = blockIdx.x;
    float s = 0.f;
    for (int d = threadIdx.x; d < D_; d += blockDim.x) {
        float inv = __expf(-lsc[d]);
        float u = (z[b * LDP + d] - loc[d]) * inv;
        s += lsc[d] + 0.5f * u * u;
    }
    s = block_reduce_sum(s);
    if (threadIdx.x == 0) {
        const float c = 0.5f * 550.f * 1.8378770664093453f;
        out[b] = lq[b] + slog[0] + slog[1] + slog[2] - c - s;
    }
}

// ---------------- launch ----------------
extern "C" void kernel_launch(void* const* d_in, const int* in_sizes, int n_in,
                              void* d_out, int out_size)
{
    (void)in_sizes; (void)n_in; (void)out_size;
    const float* x      = (const float*)d_in[0];
    const float* loc    = (const float*)d_in[1];
    const float* lsc    = (const float*)d_in[2];
    const float* Wi     = (const float*)d_in[3];
    const float* bi     = (const float*)d_in[4];
    const float* Wb     = (const float*)d_in[5];
    const float* bb     = (const float*)d_in[6];
    const float* Wo     = (const float*)d_in[7];
    const float* bo     = (const float*)d_in[8];
    const float* uw_u   = (const float*)d_in[9];
    const float* uh_u   = (const float*)d_in[10];
    const float* ud_u   = (const float*)d_in[11];
    const float* lower  = (const float*)d_in[12];
    const float* upper  = (const float*)d_in[13];
    const float* lu_ud  = (const float*)d_in[14];
    const float* lu_b   = (const float*)d_in[15];
    const int*   perms  = (const int*)d_in[16];
    float* outp = (float*)d_out;

    float *z, *zn, *LT, *UpT, *ApT0, *ident, *t, *lq, *slog, *kn0, *wop0, *wip0, *wbp0;
    cudaGetSymbolAddress((void**)&z,     g_z);
    cudaGetSymbolAddress((void**)&zn,    g_zn);
    cudaGetSymbolAddress((void**)&LT,    g_LT);
    cudaGetSymbolAddress((void**)&UpT,   g_UpT);
    cudaGetSymbolAddress((void**)&ApT0,  g_ApT);
    cudaGetSymbolAddress((void**)&ident, g_id);
    cudaGetSymbolAddress((void**)&t,     g_t);
    cudaGetSymbolAddress((void**)&lq,    g_lq);
    cudaGetSymbolAddress((void**)&slog,  g_slog);
    cudaGetSymbolAddress((void**)&kn0,   g_kn);
    cudaGetSymbolAddress((void**)&wop0,  g_Wop);
    cudaGetSymbolAddress((void**)&wip0,  g_Wip);
    cudaGetSymbolAddress((void**)&wbp0,  g_Wbp);

    float* ApT[3]; float* kn[3]; float* wop[3]; float* wip[3]; float* wbp[3];
    for (int i = 0; i < 3; i++) {
        ApT[i] = ApT0 + (size_t)i * MATR * LDP;
        kn[i]  = kn0  + (size_t)i * F_ * 27;
        wop[i] = wop0 + (size_t)i * H_ * LDW;
        wip[i] = wip0 + (size_t)i * 288 * H_;
        wbp[i] = wbp0 + (size_t)i * 4 * H_ * H_;
    }

    constexpr int RESNET_SMEM = (64 * 132 + 32 * 136 + 32 * 36) * 4;  // 55808 B
    constexpr int WOSP_SMEM   = 64 * 200 * 4;                          // 51200 B
    constexpr int PREP_TOTAL = 288 * H_ + 4 * H_ * H_ + H_ * LDW;

    // One-time setup. If any stream/event creation fails, fall back to the
    // single-stream schedule (events become same-stream no-ops).
    static cudaStream_t sside = nullptr;
    static cudaEvent_t ev_fork;
    static cudaEvent_t ev_apt[3], ev_prep[3], ev_kn[3];
    static bool streams_ok = false;
    static bool init_done = false;
    if (!init_done) {
        cudaFuncSetAttribute(wo_spline_tc,
                             cudaFuncAttributeMaxDynamicSharedMemorySize, WOSP_SMEM);
        cudaFuncSetAttribute(resnet_fused,
                             cudaFuncAttributeMaxDynamicSharedMemorySize, RESNET_SMEM);
        bool ok = (cudaStreamCreateWithFlags(&sside, cudaStreamNonBlocking) == cudaSuccess);
        ok = ok && (cudaEventCreateWithFlags(&ev_fork, cudaEventDisableTiming) == cudaSuccess);
        for (int i = 0; i < 3 && ok; i++) {
            ok = ok && (cudaEventCreateWithFlags(&ev_apt[i],  cudaEventDisableTiming) == cudaSuccess);
            ok = ok && (cudaEventCreateWithFlags(&ev_prep[i], cudaEventDisableTiming) == cudaSuccess);
            ok = ok && (cudaEventCreateWithFlags(&ev_kn[i],   cudaEventDisableTiming) == cudaSuccess);
        }
        streams_ok = ok;
        init_done = true;
    }

    cudaStream_t SP = streams_ok ? sside : (cudaStream_t)0;

    // ---- fork side stream for all per-layer prep (independent of main chain) ----
    if (streams_ok) {
        cudaEventRecord(ev_fork, 0);
        cudaStreamWaitEvent(SP, ev_fork, 0);
    }

    for (int i = 2; i >= 0; i--) {
        build_lt_upt_kernel<<<dim3((D_ + 255) / 256, D_, 2), 256, 0, SP>>>(
            lower + i * D_ * D_, upper + i * D_ * D_,
            lu_ud + i * D_, perms + i * D_, LT, UpT);
        apt_gemm_tc<<<dim3((D_ + 63) / 64, (D_ + 127) / 128), 256, 0, SP>>>(
            UpT, LT, ApT[i]);
        if (streams_ok) cudaEventRecord(ev_apt[i], SP);
        prep_weights_kernel<<<(PREP_TOTAL + 255) / 256, 256, 0, SP>>>(
            Wi + i * F_ * H_, Wb + i * 4 * H_ * H_, Wo + i * H_ * OUT_,
            wip[i], wbp[i], wop[i]);
        if (streams_ok) cudaEventRecord(ev_prep[i], SP);
        ident_knots_kernel<<<(F_ + 255) / 256, 256, 0, SP>>>(
            uw_u + i * F_ * 8, uh_u + i * F_ * 8, ud_u + i * F_ * 7, kn[i]);
        if (streams_ok) cudaEventRecord(ev_kn[i], SP);
    }

    // ---- main chain on the capture (default) stream ----
    copy_pad_kernel<<<(B_ * D_ + 255) / 256, 256>>>(x, z);
    zero_kernel<<<(B_ + 255) / 256, 256>>>(lq, B_);
    sumlog_kernel<<<3, 256>>>(lu_ud, slog);

    for (int i = 2; i >= 0; i--) {
        if (streams_ok) cudaStreamWaitEvent(0, ev_apt[i], 0);
        lu_gemm_tc<<<dim3((D_ + 63) / 64, B_ / 128), 256>>>(z, ApT[i], lu_b + i * D_, zn);
        if (streams_ok) cudaStreamWaitEvent(0, ev_kn[i], 0);
        ident_eval_kernel<<<dim3((F_ + 31) / 32, B_ / 8), 256>>>(
            zn, kn[i], ident, z, lq);
        if (streams_ok) cudaStreamWaitEvent(0, ev_prep[i], 0);
        resnet_fused<<<B_ / 32, 256, RESNET_SMEM>>>(
            ident, wip[i], bi + i * H_, wbp[i], bb + i * 4 * H_, t);
        wo_spline_tc<<<dim3((F_ + 7) / 8, B_ / 64), 256, WOSP_SMEM>>>(
            t, wop[i], bo + i * OUT_, zn, z, lq);
    }

    final_kernel<<<B_, 256>>>(z, loc, lsc, lq, slog, outp);
}

// round 17
// speedup vs baseline: 1.0993x; 1.0317x over previous
#include <cuda_runtime.h>
#include <math.h>

// ---------------- problem constants ----------------
namespace {
constexpr int D_   = 550;
constexpr int LDP  = 560;    // padded lead dim: 35*16, all pads guaranteed zero
constexpr int MATR = 640;    // matrix buffer rows (128-tile coverage, zero pads)
constexpr int F_   = 275;
constexpr int LDF  = 288;    // padded ident stride (36*8, zero pads -> guard-free K)
constexpr int B_   = 4096;   // N*T = 8*512
constexpr int H_   = 128;
constexpr int OUT_ = 6325;   // F_*(3*8-1)
constexpr int LDW  = 6720;   // padded Wo cols: 280 features * 24
}

// ---------------- scratch (device globals; no allocs allowed) ----------------
__device__ float g_z  [B_*LDP];     // ping buffer; zero-init => pad cols stay 0
__device__ float g_zn [B_*LDP];     // pong buffer
__device__ float g_LT [MATR*LDP];   // side-stream private
__device__ float g_UpT[MATR*LDP];   // side-stream private
__device__ float g_ApT[3][MATR*LDP];// per-layer, tf32-rounded
__device__ float g_id [B_*LDF];     // tf32-rounded; zero-init pads
__device__ float g_t  [B_*H_];
__device__ float g_lq [B_];
__device__ float g_slog[3];
__device__ float g_kn [3][F_*27];   // per-layer ident knots
__device__ float g_Wop[3][H_*LDW];  // per-layer padded Wo, tf32-rounded
__device__ float g_Wip[3][288*H_];  // per-layer padded Wi, tf32-rounded
__device__ float g_Wbp[3][4*H_*H_]; // per-layer Wb, tf32-rounded

// ---------------- helpers ----------------
__device__ __forceinline__ float softplus_acc(float x) {
    return (x > 20.f) ? x : log1pf(__expf(x));
}
__device__ __forceinline__ float softplus_fast(float x) {
    return (x > 15.f) ? x : __logf(1.f + __expf(x));
}

__device__ __forceinline__ unsigned f2tf32(float x) {
    unsigned r; asm("cvt.rna.tf32.f32 %0, %1;" : "=r"(r) : "f"(x)); return r;
}
__device__ __forceinline__ float roundtf(float x) {
    return __uint_as_float(f2tf32(x));
}

__device__ __forceinline__ void mma_tf32(float* c,
    unsigned a0, unsigned a1, unsigned a2, unsigned a3,
    unsigned b0, unsigned b1)
{
    asm volatile(
        "mma.sync.aligned.m16n8k8.row.col.f32.tf32.tf32.f32 "
        "{%0,%1,%2,%3}, {%4,%5,%6,%7}, {%8,%9}, {%0,%1,%2,%3};\n"
        : "+f"(c[0]), "+f"(c[1]), "+f"(c[2]), "+f"(c[3])
        : "r"(a0), "r"(a1), "r"(a2), "r"(a3), "r"(b0), "r"(b1));
}

__device__ __forceinline__ float block_reduce_sum(float v) {
    __shared__ float sred[32];
    int tid = threadIdx.x;
    #pragma unroll
    for (int o = 16; o > 0; o >>= 1) v += __shfl_down_sync(0xffffffffu, v, o);
    if ((tid & 31) == 0) sred[tid >> 5] = v;
    __syncthreads();
    if (tid < 32) {
        int nw = (blockDim.x + 31) >> 5;
        v = (tid < nw) ? sred[tid] : 0.f;
        #pragma unroll
        for (int o = 16; o > 0; o >>= 1) v += __shfl_down_sync(0xffffffffu, v, o);
    }
    return v;
}

// Table-driven inverse RQS (knots K: cw[9], ch[9], dd[9]).
__device__ __forceinline__ float rqs_table(const float* __restrict__ K, float x,
                                           float& ldv)
{
    const float TB = 3.f;
    bool inside = (x >= -TB) && (x <= TB);
    float xi = fminf(fmaxf(x, -TB), TB);

    int cnt = 0;
    #pragma unroll
    for (int k = 0; k < 9; k++) {
        float lo = K[9 + k] + (k == 8 ? 1e-6f : 0.f);
        cnt += (xi >= lo) ? 1 : 0;
    }
    int idx = cnt - 1; idx = idx < 0 ? 0 : (idx > 7 ? 7 : idx);

    float icw = K[idx],     iw = K[idx + 1] - icw;
    float ich = K[9 + idx], ih = K[10 + idx] - ich;
    float d0  = K[18 + idx], d1 = K[19 + idx];

    float delta = __fdividef(ih, iw);
    float t  = xi - ich;
    float s2 = d0 + d1 - 2.f * delta;
    float aa = t * s2 + ih * (delta - d0);
    float bb = ih * d0 - t * s2;
    float cc = -delta * t;
    float disc = bb * bb - 4.f * aa * cc;
    float sq = disc * __frsqrt_rn(fmaxf(disc, 1e-37f));
    float root = __fdividef(2.f * cc, -bb - sq);
    float o = root * iw + icw;
    float tm = root * (1.f - root);
    float den = delta + s2 * tm;
    float omr = 1.f - root;
    float dnum = delta * delta * (d1 * root * root + 2.f * delta * tm + d0 * omr * omr);
    float l = -__logf(__fdividef(dnum, den * den));

    ldv = inside ? l : 0.f;
    return inside ? o : x;
}

// Fast inverse RQS, params in registers (conditional path).
__device__ __forceinline__ void rqs_fast(float x, const float* uw, const float* uh,
                                         const float* ud7, float& out, float& ld)
{
    const float TB = 3.f;
    bool inside = (x >= -TB) && (x <= TB);
    float xi = fminf(fmaxf(x, -TB), TB);

    float cw[9], ch[9];
    {
        float m = uw[0];
        #pragma unroll
        for (int k = 1; k < 8; k++) m = fmaxf(m, uw[k]);
        float e[8]; float s = 0.f;
        #pragma unroll
        for (int k = 0; k < 8; k++) { e[k] = __expf(uw[k] - m); s += e[k]; }
        float inv = __fdividef(1.f, s);
        float cum = 0.f;
        cw[0] = -TB;
        #pragma unroll
        for (int k = 0; k < 7; k++) { cum += 0.001f + 0.992f * e[k] * inv; cw[k+1] = 6.f * cum - 3.f; }
        cw[8] = TB;
    }
    {
        float m = uh[0];
        #pragma unroll
        for (int k = 1; k < 8; k++) m = fmaxf(m, uh[k]);
        float e[8]; float s = 0.f;
        #pragma unroll
        for (int k = 0; k < 8; k++) { e[k] = __expf(uh[k] - m); s += e[k]; }
        float inv = __fdividef(1.f, s);
        float cum = 0.f;
        ch[0] = -TB;
        #pragma unroll
        for (int k = 0; k < 7; k++) { cum += 0.001f + 0.992f * e[k] * inv; ch[k+1] = 6.f * cum - 3.f; }
        ch[8] = TB;
    }

    int cnt = 0;
    #pragma unroll
    for (int k = 0; k < 9; k++) {
        float lo = ch[k] + (k == 8 ? 1e-6f : 0.f);
        cnt += (xi >= lo) ? 1 : 0;
    }
    int idx = cnt - 1; idx = idx < 0 ? 0 : (idx > 7 ? 7 : idx);

    float icw = 0.f, iw = 1.f, ich = 0.f, ih = 1.f;
    float u0 = 0.f, u1 = 0.f;
    #pragma unroll
    for (int k = 0; k < 8; k++) {
        if (k == idx) {
            icw = cw[k]; iw = cw[k+1] - cw[k];
            ich = ch[k]; ih = ch[k+1] - ch[k];
        }
    }
    #pragma unroll
    for (int k = 0; k < 7; k++) {
        if (k == idx - 1) u0 = ud7[k];
        if (k == idx)     u1 = ud7[k];
    }
    float d0 = (idx == 0) ? 1.f : 0.001f + softplus_fast(u0);
    float d1 = (idx == 7) ? 1.f : 0.001f + softplus_fast(u1);

    float delta = __fdividef(ih, iw);
    float t  = xi - ich;
    float s2 = d0 + d1 - 2.f * delta;
    float aa = t * s2 + ih * (delta - d0);
    float bb = ih * d0 - t * s2;
    float cc = -delta * t;
    float disc = bb * bb - 4.f * aa * cc;
    float sq = disc * __frsqrt_rn(fmaxf(disc, 1e-37f));
    float root = __fdividef(2.f * cc, -bb - sq);
    float o = root * iw + icw;
    float tm = root * (1.f - root);
    float den = delta + s2 * tm;
    float omr = 1.f - root;
    float dnum = delta * delta * (d1 * root * root + 2.f * delta * tm + d0 * omr * omr);
    float l = -__logf(__fdividef(dnum, den * den));

    out = inside ? o : x;
    ld  = inside ? l : 0.f;
}

// ---------------- small kernels ----------------
__global__ void zero_kernel(float* p, int n) {
    int i = blockIdx.x * blockDim.x + threadIdx.x;
    if (i < n) p[i] = 0.f;
}

__global__ void copy_pad_kernel(const float* __restrict__ x, float* __restrict__ z) {
    int i = blockIdx.x * blockDim.x + threadIdx.x;
    if (i >= B_ * D_) return;
    int b = i / D_, d = i % D_;
    z[b * LDP + d] = x[i];
}

__global__ void sumlog_kernel(const float* __restrict__ lu_ud, float* __restrict__ out) {
    int i = blockIdx.x;
    float s = 0.f;
    for (int d = threadIdx.x; d < D_; d += blockDim.x)
        s += __logf(softplus_acc(lu_ud[i * D_ + d]) + 0.001f);
    s = block_reduce_sum(s);
    if (threadIdx.x == 0) out[i] = s;
}

// Combined per-layer weight prep (tf32-rounded at materialization).
__global__ void prep_weights_kernel(const float* __restrict__ Wi,
                                    const float* __restrict__ Wb,
                                    const float* __restrict__ Wo,
                                    float* __restrict__ Wip,
                                    float* __restrict__ Wbp,
                                    float* __restrict__ Wop)
{
    constexpr int N_WIP = 288 * H_;
    constexpr int N_WBP = 4 * H_ * H_;
    constexpr int N_WOP = H_ * LDW;
    int idx = blockIdx.x * blockDim.x + threadIdx.x;
    if (idx < N_WIP) {
        int f = idx / H_, h = idx % H_;
        Wip[idx] = (f < F_) ? roundtf(Wi[f * H_ + h]) : 0.f;
    } else if (idx < N_WIP + N_WBP) {
        int j = idx - N_WIP;
        Wbp[j] = roundtf(Wb[j]);
    } else if (idx < N_WIP + N_WBP + N_WOP) {
        int j = idx - N_WIP - N_WBP;
        int k = j / LDW, c = j % LDW;
        int f = c / 24, o = c % 24;
        float v = 0.f;
        if (o < 23 && f < F_) v = roundtf(Wo[k * OUT_ + f * 23 + o]);
        Wop[j] = v;
    }
}

// Per-f knots for the unconditional (ident) spline
__global__ void ident_knots_kernel(const float* __restrict__ uw_u,
                                   const float* __restrict__ uh_u,
                                   const float* __restrict__ ud_u,
                                   float* __restrict__ kn)
{
    int f = blockIdx.x * blockDim.x + threadIdx.x;
    if (f >= F_) return;
    const float TB = 3.f;
    float* o = kn + f * 27;
    {
        const float* u = uw_u + f * 8;
        float m = u[0];
        #pragma unroll
        for (int k = 1; k < 8; k++) m = fmaxf(m, u[k]);
        float e[8]; float s = 0.f;
        #pragma unroll
        for (int k = 0; k < 8; k++) { e[k] = __expf(u[k] - m); s += e[k]; }
        float inv = 1.f / s;
        float cum = 0.f;
        o[0] = -TB;
        #pragma unroll
        for (int k = 0; k < 7; k++) { cum += 0.001f + 0.992f * e[k] * inv; o[k+1] = 6.f * cum - 3.f; }
        o[8] = TB;
    }
    {
        const float* u = uh_u + f * 8;
        float m = u[0];
        #pragma unroll
        for (int k = 1; k < 8; k++) m = fmaxf(m, u[k]);
        float e[8]; float s = 0.f;
        #pragma unroll
        for (int k = 0; k < 8; k++) { e[k] = __expf(u[k] - m); s += e[k]; }
        float inv = 1.f / s;
        float cum = 0.f;
        o[9] = -TB;
        #pragma unroll
        for (int k = 0; k < 7; k++) { cum += 0.001f + 0.992f * e[k] * inv; o[10+k] = 6.f * cum - 3.f; }
        o[17] = TB;
    }
    o[18] = 1.f; o[26] = 1.f;
    #pragma unroll
    for (int k = 0; k < 7; k++) o[19 + k] = 0.001f + softplus_acc(ud_u[f * 7 + k]);
}

// Materialize LT[m,d] = L[d,m] (unit diag) and UpT[perm[k], m] = Udense[m,k].
__global__ void build_lt_upt_kernel(const float* __restrict__ lower,
                                    const float* __restrict__ upper,
                                    const float* __restrict__ lu_ud,
                                    const int* __restrict__ perm,
                                    float* __restrict__ LT, float* __restrict__ UpT)
{
    int c = blockIdx.x * blockDim.x + threadIdx.x;
    int rr = blockIdx.y;
    if (c >= D_) return;
    if (blockIdx.z == 0) {
        int m = rr, d = c;
        float v = (m < d) ? lower[d * D_ + m] : ((m == d) ? 1.f : 0.f);
        LT[m * LDP + d] = v;
    } else {
        int k = rr, m = c;
        float v;
        if (m < k)       v = upper[m * D_ + k];
        else if (m == k) v = softplus_acc(lu_ud[k]) + 0.001f;
        else             v = 0.f;
        UpT[perm[k] * LDP + m] = v;
    }
}

// ---------------- tf32 TC GEMM core (128m x 64n, double-buffered) ------------
template<bool RND_B, bool HASB, bool TFOUT>
__device__ __forceinline__ void tc_gemm_128x64(
    const float* __restrict__ A, int lda,
    const float* __restrict__ Bm, int ldb,
    const float* __restrict__ bias, float* __restrict__ C, int ldc,
    int m0, int n0, int K, int Nvalid,
    float (*As)[128][20], float (*Bs)[16][72])
{
    int tid  = threadIdx.x;
    int warp = tid >> 5, lane = tid & 31;
    int mwarp = (warp & 3) * 32;
    int nwarp = (warp >> 2) * 32;
    int g = lane >> 2, t4 = lane & 3;

    int arow0 = tid >> 2,            acol = (tid & 3) << 2;
    int arow1 = (tid + 256) >> 2;
    int brow  = tid >> 4,            bcol = (tid & 15) << 2;

    float c[2][4][4];
    #pragma unroll
    for (int i = 0; i < 2; i++)
        #pragma unroll
        for (int j = 0; j < 4; j++)
            c[i][j][0] = c[i][j][1] = c[i][j][2] = c[i][j][3] = 0.f;

    float4 sA0, sA1, sB;
    auto fetch = [&](int kc) {
        sA0 = *reinterpret_cast<const float4*>(&A[(m0 + arow0) * lda + kc + acol]);
        sA1 = *reinterpret_cast<const float4*>(&A[(m0 + arow1) * lda + kc + acol]);
        sB  = *reinterpret_cast<const float4*>(&Bm[(kc + brow) * ldb + n0 + bcol]);
    };
    auto store = [&](int buf) {
        float4 v = sA0;
        v.x = roundtf(v.x); v.y = roundtf(v.y); v.z = roundtf(v.z); v.w = roundtf(v.w);
        *reinterpret_cast<float4*>(&As[buf][arow0][acol]) = v;
        v = sA1;
        v.x = roundtf(v.x); v.y = roundtf(v.y); v.z = roundtf(v.z); v.w = roundtf(v.w);
        *reinterpret_cast<float4*>(&As[buf][arow1][acol]) = v;
        float4 w = sB;
        if (RND_B) {
            w.x = roundtf(w.x); w.y = roundtf(w.y);
            w.z = roundtf(w.z); w.w = roundtf(w.w);
        }
        *reinterpret_cast<float4*>(&Bs[buf][brow][bcol]) = w;
    };

    int NIT = K / 16;
    fetch(0);
    store(0);
    __syncthreads();

    for (int it = 0; it < NIT; it++) {
        int buf = it & 1;
        if (it + 1 < NIT) fetch((it + 1) * 16);
        #pragma unroll
        for (int k8 = 0; k8 < 16; k8 += 8) {
            #pragma unroll
            for (int mf = 0; mf < 2; mf++) {
                int mb = mwarp + mf * 16;
                unsigned a0 = __float_as_uint(As[buf][mb + g][k8 + t4]);
                unsigned a1 = __float_as_uint(As[buf][mb + g + 8][k8 + t4]);
                unsigned a2 = __float_as_uint(As[buf][mb + g][k8 + t4 + 4]);
                unsigned a3 = __float_as_uint(As[buf][mb + g + 8][k8 + t4 + 4]);
                #pragma unroll
                for (int nf = 0; nf < 4; nf++) {
                    unsigned b0r = __float_as_uint(Bs[buf][k8 + t4][nwarp + nf * 8 + g]);
                    unsigned b1r = __float_as_uint(Bs[buf][k8 + t4 + 4][nwarp + nf * 8 + g]);
                    mma_tf32(c[mf][nf], a0, a1, a2, a3, b0r, b1r);
                }
            }
        }
        if (it + 1 < NIT) store(buf ^ 1);
        __syncthreads();
    }

    #pragma unroll
    for (int mf = 0; mf < 2; mf++) {
        int r0 = m0 + mwarp + mf * 16 + g;
        int r1 = r0 + 8;
        #pragma unroll
        for (int nf = 0; nf < 4; nf++) {
            int cA = n0 + nwarp + nf * 8 + t4 * 2;
            int cB = cA + 1;
            if (cA < Nvalid) {
                float v0 = c[mf][nf][0] + (HASB ? bias[cA] : 0.f);
                float v2 = c[mf][nf][2] + (HASB ? bias[cA] : 0.f);
                C[r0 * ldc + cA] = TFOUT ? roundtf(v0) : v0;
                C[r1 * ldc + cA] = TFOUT ? roundtf(v2) : v2;
            }
            if (cB < Nvalid) {
                float v1 = c[mf][nf][1] + (HASB ? bias[cB] : 0.f);
                float v3 = c[mf][nf][3] + (HASB ? bias[cB] : 0.f);
                C[r0 * ldc + cB] = TFOUT ? roundtf(v1) : v1;
                C[r1 * ldc + cB] = TFOUT ? roundtf(v3) : v3;
            }
        }
    }
}

// ApT = UpT @ LT (both fp32, rounded in-loop; output rounded)
__global__ void __launch_bounds__(256)
apt_gemm_tc(const float* __restrict__ UpT, const float* __restrict__ LT,
            float* __restrict__ ApT)
{
    __shared__ __align__(16) float As[2][128][20];
    __shared__ __align__(16) float Bs[2][16][72];
    tc_gemm_128x64<true, false, true>(
        UpT, LDP, LT, LDP, nullptr, ApT, LDP,
        blockIdx.y * 128, blockIdx.x * 64, LDP, D_, As, Bs);
}

// ---------------- fused LU GEMM + ident spline epilogue ----------------------
// dst = src @ ApT + bias; even cols additionally pass through the per-feature
// RQS spline (knots kn), writing spline-out to dst even cols + ident (tf32)
// and accumulating logdet into lq. Odd cols stay raw (consumed by wo_spline).
__global__ void __launch_bounds__(256)
lu_gemm_fused(const float* __restrict__ src, const float* __restrict__ ApT,
              const float* __restrict__ bias, float* __restrict__ dst,
              const float* __restrict__ kn, float* __restrict__ ident,
              float* __restrict__ lq)
{
    __shared__ __align__(16) float As[2][128][20];
    __shared__ __align__(16) float Bs[2][16][72];

    int tid  = threadIdx.x;
    int warp = tid >> 5, lane = tid & 31;
    int mwarp = (warp & 3) * 32;
    int nwarp = (warp >> 2) * 32;
    int m0 = blockIdx.y * 128;
    int n0 = blockIdx.x * 64;
    int g = lane >> 2, t4 = lane & 3;

    int arow0 = tid >> 2,            acol = (tid & 3) << 2;
    int arow1 = (tid + 256) >> 2;
    int brow  = tid >> 4,            bcol = (tid & 15) << 2;

    float c[2][4][4];
    #pragma unroll
    for (int i = 0; i < 2; i++)
        #pragma unroll
        for (int j = 0; j < 4; j++)
            c[i][j][0] = c[i][j][1] = c[i][j][2] = c[i][j][3] = 0.f;

    float4 sA0, sA1, sB;
    auto fetch = [&](int kc) {
        sA0 = *reinterpret_cast<const float4*>(&src[(m0 + arow0) * LDP + kc + acol]);
        sA1 = *reinterpret_cast<const float4*>(&src[(m0 + arow1) * LDP + kc + acol]);
        sB  = *reinterpret_cast<const float4*>(&ApT[(kc + brow) * LDP + n0 + bcol]);
    };
    auto store = [&](int buf) {
        float4 v = sA0;
        v.x = roundtf(v.x); v.y = roundtf(v.y); v.z = roundtf(v.z); v.w = roundtf(v.w);
        *reinterpret_cast<float4*>(&As[buf][arow0][acol]) = v;
        v = sA1;
        v.x = roundtf(v.x); v.y = roundtf(v.y); v.z = roundtf(v.z); v.w = roundtf(v.w);
        *reinterpret_cast<float4*>(&As[buf][arow1][acol]) = v;
        *reinterpret_cast<float4*>(&Bs[buf][brow][bcol]) = sB;
    };

    constexpr int NIT = LDP / 16;  // 35
    fetch(0);
    store(0);
    __syncthreads();

    for (int it = 0; it < NIT; it++) {
        int buf = it & 1;
        if (it + 1 < NIT) fetch((it + 1) * 16);
        #pragma unroll
        for (int k8 = 0; k8 < 16; k8 += 8) {
            #pragma unroll
            for (int mf = 0; mf < 2; mf++) {
                int mb = mwarp + mf * 16;
                unsigned a0 = __float_as_uint(As[buf][mb + g][k8 + t4]);
                unsigned a1 = __float_as_uint(As[buf][mb + g + 8][k8 + t4]);
                unsigned a2 = __float_as_uint(As[buf][mb + g][k8 + t4 + 4]);
                unsigned a3 = __float_as_uint(As[buf][mb + g + 8][k8 + t4 + 4]);
                #pragma unroll
                for (int nf = 0; nf < 4; nf++) {
                    unsigned b0r = __float_as_uint(Bs[buf][k8 + t4][nwarp + nf * 8 + g]);
                    unsigned b1r = __float_as_uint(Bs[buf][k8 + t4 + 4][nwarp + nf * 8 + g]);
                    mma_tf32(c[mf][nf], a0, a1, a2, a3, b0r, b1r);
                }
            }
        }
        if (it + 1 < NIT) store(buf ^ 1);
        __syncthreads();
    }

    // Load this block's 32-feature knot tile into (now free) stage smem.
    float* kns = reinterpret_cast<float*>(As);   // 32*27 floats << stage size
    int fbase = n0 >> 1;
    for (int j = tid; j < 32 * 27; j += 256) {
        int fl = j / 27, e = j % 27;
        int f = fbase + fl;
        kns[j] = (f < F_) ? kn[f * 27 + e] : 0.f;
    }
    __syncthreads();

    float ldrow[4] = {0.f, 0.f, 0.f, 0.f};

    #pragma unroll
    for (int mf = 0; mf < 2; mf++) {
        int r0 = m0 + mwarp + mf * 16 + g;
        int r1 = r0 + 8;
        #pragma unroll
        for (int nf = 0; nf < 4; nf++) {
            int cA = n0 + nwarp + nf * 8 + t4 * 2;   // always even
            int cB = cA + 1;
            if (cA < D_) {
                float vA0 = c[mf][nf][0] + bias[cA];
                float vA1 = c[mf][nf][2] + bias[cA];
                const float* K = kns + (cA / 2 - fbase) * 27;
                float l0, l1;
                float o0 = rqs_table(K, vA0, l0);
                float o1 = rqs_table(K, vA1, l1);
                dst[r0 * LDP + cA] = o0;
                dst[r1 * LDP + cA] = o1;
                int f = cA >> 1;
                ident[r0 * LDF + f] = roundtf(o0);
                ident[r1 * LDF + f] = roundtf(o1);
                ldrow[mf * 2 + 0] += l0;
                ldrow[mf * 2 + 1] += l1;
            }
            if (cB < D_) {
                dst[r0 * LDP + cB] = c[mf][nf][1] + bias[cB];
                dst[r1 * LDP + cB] = c[mf][nf][3] + bias[cB];
            }
        }
    }
    // reduce over the 4-lane t4 group (same rows), then one atomic per row
    #pragma unroll
    for (int k = 0; k < 4; k++) {
        ldrow[k] += __shfl_xor_sync(0xffffffffu, ldrow[k], 1);
        ldrow[k] += __shfl_xor_sync(0xffffffffu, ldrow[k], 2);
    }
    if (t4 == 0) {
        int rbase = m0 + mwarp + g;
        atomicAdd(&lq[rbase],      ldrow[0]);
        atomicAdd(&lq[rbase + 8],  ldrow[1]);
        atomicAdd(&lq[rbase + 16], ldrow[2]);
        atomicAdd(&lq[rbase + 24], ldrow[3]);
    }
}

// ---------------- fused tf32 resnet: t = resnet(ident) per 32-row block ------
__global__ void __launch_bounds__(256)
resnet_fused(const float* __restrict__ ident, const float* __restrict__ Wip,
             const float* __restrict__ bi, const float* __restrict__ Wbp,
             const float* __restrict__ bb, float* __restrict__ tout)
{
    extern __shared__ float smf[];
    float (*Ts)[132] = reinterpret_cast<float(*)[132]>(smf);
    float (*Rs)[132] = reinterpret_cast<float(*)[132]>(smf + 32 * 132);
    float (*Ws)[136] = reinterpret_cast<float(*)[136]>(smf + 64 * 132);
    float (*As)[36]  = reinterpret_cast<float(*)[36]>(smf + 64 * 132 + 32 * 136);

    int tid = threadIdx.x, warp = tid >> 5, lane = tid & 31;
    int mw = (warp & 1) * 16;
    int nw = (warp >> 1) * 32;
    int m0 = blockIdx.x * 32;
    int g = lane >> 2, t4 = lane & 3;

    float c[4][4];

    #pragma unroll
    for (int i = 0; i < 4; i++) c[i][0] = c[i][1] = c[i][2] = c[i][3] = 0.f;

    for (int kc = 0; kc < 288; kc += 32) {
        __syncthreads();
        {
            int r = tid >> 3, c4 = (tid & 7) << 2;
            *reinterpret_cast<float4*>(&As[r][c4]) =
                *reinterpret_cast<const float4*>(&ident[(m0 + r) * LDF + kc + c4]);
        }
        #pragma unroll
        for (int i = 0; i < 4; i++) {
            int idx = tid + i * 256;
            int r = idx >> 5, c4 = (idx & 31) << 2;
            *reinterpret_cast<float4*>(&Ws[r][c4]) =
                *reinterpret_cast<const float4*>(&Wip[(kc + r) * H_ + c4]);
        }
        __syncthreads();
        #pragma unroll
        for (int k8 = 0; k8 < 32; k8 += 8) {
            unsigned a0 = __float_as_uint(As[mw + g][k8 + t4]);
            unsigned a1 = __float_as_uint(As[mw + g + 8][k8 + t4]);
            unsigned a2 = __float_as_uint(As[mw + g][k8 + t4 + 4]);
            unsigned a3 = __float_as_uint(As[mw + g + 8][k8 + t4 + 4]);
            #pragma unroll
            for (int nf = 0; nf < 4; nf++) {
                unsigned b0r = __float_as_uint(Ws[k8 + t4][nw + nf * 8 + g]);
                unsigned b1r = __float_as_uint(Ws[k8 + t4 + 4][nw + nf * 8 + g]);
                mma_tf32(c[nf], a0, a1, a2, a3, b0r, b1r);
            }
        }
    }
    {
        int r0 = mw + g, r1 = r0 + 8;
        #pragma unroll
        for (int nf = 0; nf < 4; nf++) {
            int cA = nw + nf * 8 + t4 * 2, cB = cA + 1;
            Ts[r0][cA] = c[nf][0] + bi[cA];
            Ts[r0][cB] = c[nf][1] + bi[cB];
            Ts[r1][cA] = c[nf][2] + bi[cA];
            Ts[r1][cB] = c[nf][3] + bi[cB];
        }
    }

    #pragma unroll 1
    for (int j = 0; j < 4; j++) {
        float (*S)[132] = (j & 1) ? Rs : Ts;
        const float* W  = Wbp + j * H_ * H_;
        const float* bv = bb + j * H_;
        #pragma unroll
        for (int i = 0; i < 4; i++) c[i][0] = c[i][1] = c[i][2] = c[i][3] = 0.f;

        for (int kc = 0; kc < H_; kc += 32) {
            __syncthreads();
            #pragma unroll
            for (int i = 0; i < 4; i++) {
                int idx = tid + i * 256;
                int r = idx >> 5, c4 = (idx & 31) << 2;
                *reinterpret_cast<float4*>(&Ws[r][c4]) =
                    *reinterpret_cast<const float4*>(&W[(kc + r) * H_ + c4]);
            }
            __syncthreads();
            #pragma unroll
            for (int k8 = 0; k8 < 32; k8 += 8) {
                int k = kc + k8;
                unsigned a0 = f2tf32(fmaxf(S[mw + g][k + t4], 0.f));
                unsigned a1 = f2tf32(fmaxf(S[mw + g + 8][k + t4], 0.f));
                unsigned a2 = f2tf32(fmaxf(S[mw + g][k + t4 + 4], 0.f));
                unsigned a3 = f2tf32(fmaxf(S[mw + g + 8][k + t4 + 4], 0.f));
                #pragma unroll
                for (int nf = 0; nf < 4; nf++) {
                    unsigned b0r = __float_as_uint(Ws[k8 + t4][nw + nf * 8 + g]);
                    unsigned b1r = __float_as_uint(Ws[k8 + t4 + 4][nw + nf * 8 + g]);
                    mma_tf32(c[nf], a0, a1, a2, a3, b0r, b1r);
                }
            }
        }
        {
            int r0 = mw + g, r1 = r0 + 8;
            #pragma unroll
            for (int nf = 0; nf < 4; nf++) {
                int cA = nw + nf * 8 + t4 * 2, cB = cA + 1;
                if (j & 1) {
                    Ts[r0][cA] += c[nf][0] + bv[cA];
                    Ts[r0][cB] += c[nf][1] + bv[cB];
                    Ts[r1][cA] += c[nf][2] + bv[cA];
                    Ts[r1][cB] += c[nf][3] + bv[cB];
                } else {
                    Rs[r0][cA] = c[nf][0] + bv[cA];
                    Rs[r0][cB] = c[nf][1] + bv[cB];
                    Rs[r1][cA] = c[nf][2] + bv[cA];
                    Rs[r1][cB] = c[nf][3] + bv[cB];
                }
            }
        }
    }
    __syncthreads();
    #pragma unroll
    for (int i = 0; i < 4; i++) {
        int idx = tid + i * 256;
        int r = idx >> 5, c4 = (idx & 31) << 2;
        *reinterpret_cast<float4*>(&tout[(m0 + r) * H_ + c4]) =
            *reinterpret_cast<const float4*>(&Ts[r][c4]);
    }
}

// ---------------- tf32 TC fused Wo GEMM + spline, double-buffered (K16) ------
__global__ void __launch_bounds__(256)
wo_spline_tc(const float* __restrict__ tmat, const float* __restrict__ Wop,
             const float* __restrict__ bo, const float* __restrict__ zn,
             float* __restrict__ zout, float* __restrict__ lq)
{
    extern __shared__ float sm[];
    float (*As)[64][20]  = reinterpret_cast<float(*)[64][20]>(sm);
    float (*Bs)[16][200] = reinterpret_cast<float(*)[16][200]>(sm + 2 * 64 * 20);
    float (*Cs)[200]     = reinterpret_cast<float(*)[200]>(sm);
    __shared__ float bos[192];

    int tid  = threadIdx.x;
    int warp = tid >> 5, lane = tid & 31;
    int mw = (warp & 3) * 16;
    int nw = (warp >> 2) * 96;
    int b0 = blockIdx.y * 64;
    int f0 = blockIdx.x * 8;
    int n0 = blockIdx.x * 192;

    for (int i = tid; i < 192; i += 256) {
        int ff = i / 24, oo = i % 24;
        int col = (f0 + ff) * 23 + oo;
        bos[i] = (oo < 23 && col < OUT_) ? bo[col] : 0.f;
    }

    float c[12][4];
    #pragma unroll
    for (int i = 0; i < 12; i++) { c[i][0] = c[i][1] = c[i][2] = c[i][3] = 0.f; }

    int g = lane >> 2, t4 = lane & 3;

    int ar = tid >> 2, ac = (tid & 3) << 2;
    int br[3], bc[3];
    #pragma unroll
    for (int i = 0; i < 3; i++) {
        int idx = tid + i * 256;
        br[i] = idx / 48; bc[i] = (idx % 48) << 2;
    }

    float4 sA, sB[3];
    auto fetch = [&](int kc) {
        sA = *reinterpret_cast<const float4*>(&tmat[(b0 + ar) * H_ + kc + ac]);
        #pragma unroll
        for (int i = 0; i < 3; i++)
            sB[i] = *reinterpret_cast<const float4*>(&Wop[(kc + br[i]) * LDW + n0 + bc[i]]);
    };
    auto store = [&](int buf) {
        As[buf][ar][ac + 0] = roundtf(sA.x);
        As[buf][ar][ac + 1] = roundtf(sA.y);
        As[buf][ar][ac + 2] = roundtf(sA.z);
        As[buf][ar][ac + 3] = roundtf(sA.w);
        #pragma unroll
        for (int i = 0; i < 3; i++)
            *reinterpret_cast<float4*>(&Bs[buf][br[i]][bc[i]]) = sB[i];
    };

    fetch(0);
    store(0);
    __syncthreads();

    #pragma unroll 1
    for (int it = 0; it < 8; it++) {
        int buf = it & 1;
        if (it + 1 < 8) fetch((it + 1) * 16);
        #pragma unroll
        for (int k8 = 0; k8 < 16; k8 += 8) {
            unsigned a0 = __float_as_uint(As[buf][mw + g][k8 + t4]);
            unsigned a1 = __float_as_uint(As[buf][mw + g + 8][k8 + t4]);
            unsigned a2 = __float_as_uint(As[buf][mw + g][k8 + t4 + 4]);
            unsigned a3 = __float_as_uint(As[buf][mw + g + 8][k8 + t4 + 4]);
            #pragma unroll
            for (int nt = 0; nt < 12; nt++) {
                unsigned b0r = __float_as_uint(Bs[buf][k8 + t4][nw + nt * 8 + g]);
                unsigned b1r = __float_as_uint(Bs[buf][k8 + t4 + 4][nw + nt * 8 + g]);
                mma_tf32(c[nt], a0, a1, a2, a3, b0r, b1r);
            }
        }
        if (it + 1 < 8) store(buf ^ 1);
        __syncthreads();
    }

    {
        int t2 = (lane & 3) * 2;
        int r0 = mw + g, r1 = r0 + 8;
        #pragma unroll
        for (int nt = 0; nt < 12; nt++) {
            int col0 = nw + nt * 8 + t2;
            int fa = col0 / 24, oa = col0 % 24;
            Cs[r0][fa * 25 + oa] = c[nt][0];
            Cs[r1][fa * 25 + oa] = c[nt][2];
            int col1 = col0 + 1;
            int fb = col1 / 24, ob = col1 % 24;
            Cs[r0][fb * 25 + ob] = c[nt][1];
            Cs[r1][fb * 25 + ob] = c[nt][3];
        }
    }
    __syncthreads();

    int f_local = tid & 7;
    int b_local = tid >> 3;
    int f = f0 + f_local;
    const float scale = 0.08838834764831845f;
    float ld0 = 0.f, ld1 = 0.f;

    if (f < F_) {
        const float* Bo = bos + f_local * 24;
        {
            const float* P = Cs[b_local] + f_local * 25;
            float uw[8], uh[8], ud7[7];
            #pragma unroll
            for (int o = 0; o < 8; o++) {
                uw[o] = (P[o] + Bo[o]) * scale;
                uh[o] = (P[8 + o] + Bo[8 + o]) * scale;
            }
            #pragma unroll
            for (int o = 0; o < 7; o++) ud7[o] = P[16 + o] + Bo[16 + o];
            int b = b0 + b_local;
            float x = zn[b * LDP + 2 * f + 1];
            float o, l;
            rqs_fast(x, uw, uh, ud7, o, l);
            zout[b * LDP + 2 * f + 1] = o;
            ld0 = l;
        }
        {
            const float* P = Cs[b_local + 32] + f_local * 25;
            float uw[8], uh[8], ud7[7];
            #pragma unroll
            for (int o = 0; o < 8; o++) {
                uw[o] = (P[o] + Bo[o]) * scale;
                uh[o] = (P[8 + o] + Bo[8 + o]) * scale;
            }
            #pragma unroll
            for (int o = 0; o < 7; o++) ud7[o] = P[16 + o] + Bo[16 + o];
            int b = b0 + b_local + 32;
            float x = zn[b * LDP + 2 * f + 1];
            float o, l;
            rqs_fast(x, uw, uh, ud7, o, l);
            zout[b * LDP + 2 * f + 1] = o;
            ld1 = l;
        }
    }
    #pragma unroll
    for (int o = 4; o > 0; o >>= 1) {
        ld0 += __shfl_xor_sync(0xffffffffu, ld0, o);
        ld1 += __shfl_xor_sync(0xffffffffu, ld1, o);
    }
    if (f_local == 0) {
        atomicAdd(&lq[b0 + b_local], ld0);
        atomicAdd(&lq[b0 + b_local + 32], ld1);
    }
}

__global__ void final_kernel(const float* __restrict__ z, const float* __restrict__ loc,
                             const float* __restrict__ lsc, const float* __restrict__ lq,
                             const float* __restrict__ slog, float* __restrict__ out)
{
    int b = blockIdx.x;
    float s = 0.f;
    for (int d = threadIdx.x; d < D_; d += blockDim.x) {
        float inv = __expf(-lsc[d]);
        float u = (z[b * LDP + d] - loc[d]) * inv;
        s += lsc[d] + 0.5f * u * u;
    }
    s = block_reduce_sum(s);
    if (threadIdx.x == 0) {
        const float c = 0.5f * 550.f * 1.8378770664093453f;
        out[b] = lq[b] + slog[0] + slog[1] + slog[2] - c - s;
    }
}

// ---------------- launch ----------------
extern "C" void kernel_launch(void* const* d_in, const int* in_sizes, int n_in,
                              void* d_out, int out_size)
{
    (void)in_sizes; (void)n_in; (void)out_size;
    const float* x      = (const float*)d_in[0];
    const float* loc    = (const float*)d_in[1];
    const float* lsc    = (const float*)d_in[2];
    const float* Wi     = (const float*)d_in[3];
    const float* bi     = (const float*)d_in[4];
    const float* Wb     = (const float*)d_in[5];
    const float* bb     = (const float*)d_in[6];
    const float* Wo     = (const float*)d_in[7];
    const float* bo     = (const float*)d_in[8];
    const float* uw_u   = (const float*)d_in[9];
    const float* uh_u   = (const float*)d_in[10];
    const float* ud_u   = (const float*)d_in[11];
    const float* lower  = (const float*)d_in[12];
    const float* upper  = (const float*)d_in[13];
    const float* lu_ud  = (const float*)d_in[14];
    const float* lu_b   = (const float*)d_in[15];
    const int*   perms  = (const int*)d_in[16];
    float* outp = (float*)d_out;

    float *zb0, *zb1, *LT, *UpT, *ApT0, *ident, *t, *lq, *slog, *kn0, *wop0, *wip0, *wbp0;
    cudaGetSymbolAddress((void**)&zb0,   g_z);
    cudaGetSymbolAddress((void**)&zb1,   g_zn);
    cudaGetSymbolAddress((void**)&LT,    g_LT);
    cudaGetSymbolAddress((void**)&UpT,   g_UpT);
    cudaGetSymbolAddress((void**)&ApT0,  g_ApT);
    cudaGetSymbolAddress((void**)&ident, g_id);
    cudaGetSymbolAddress((void**)&t,     g_t);
    cudaGetSymbolAddress((void**)&lq,    g_lq);
    cudaGetSymbolAddress((void**)&slog,  g_slog);
    cudaGetSymbolAddress((void**)&kn0,   g_kn);
    cudaGetSymbolAddress((void**)&wop0,  g_Wop);
    cudaGetSymbolAddress((void**)&wip0,  g_Wip);
    cudaGetSymbolAddress((void**)&wbp0,  g_Wbp);

    float* ApT[3]; float* kn[3]; float* wop[3]; float* wip[3]; float* wbp[3];
    for (int i = 0; i < 3; i++) {
        ApT[i] = ApT0 + (size_t)i * MATR * LDP;
        kn[i]  = kn0  + (size_t)i * F_ * 27;
        wop[i] = wop0 + (size_t)i * H_ * LDW;
        wip[i] = wip0 + (size_t)i * 288 * H_;
        wbp[i] = wbp0 + (size_t)i * 4 * H_ * H_;
    }

    constexpr int RESNET_SMEM = (64 * 132 + 32 * 136 + 32 * 36) * 4;  // 55808 B
    constexpr int WOSP_SMEM   = 64 * 200 * 4;                          // 51200 B
    constexpr int PREP_TOTAL = 288 * H_ + 4 * H_ * H_ + H_ * LDW;

    static cudaStream_t sside = nullptr;
    static cudaEvent_t ev_fork;
    static cudaEvent_t ev_apt[3], ev_prep[3], ev_kn[3];
    static bool streams_ok = false;
    static bool init_done = false;
    if (!init_done) {
        cudaFuncSetAttribute(wo_spline_tc,
                             cudaFuncAttributeMaxDynamicSharedMemorySize, WOSP_SMEM);
        cudaFuncSetAttribute(resnet_fused,
                             cudaFuncAttributeMaxDynamicSharedMemorySize, RESNET_SMEM);
        bool ok = (cudaStreamCreateWithFlags(&sside, cudaStreamNonBlocking) == cudaSuccess);
        ok = ok && (cudaEventCreateWithFlags(&ev_fork, cudaEventDisableTiming) == cudaSuccess);
        for (int i = 0; i < 3 && ok; i++) {
            ok = ok && (cudaEventCreateWithFlags(&ev_apt[i],  cudaEventDisableTiming) == cudaSuccess);
            ok = ok && (cudaEventCreateWithFlags(&ev_prep[i], cudaEventDisableTiming) == cudaSuccess);
            ok = ok && (cudaEventCreateWithFlags(&ev_kn[i],   cudaEventDisableTiming) == cudaSuccess);
        }
        streams_ok = ok;
        init_done = true;
    }

    cudaStream_t SP = streams_ok ? sside : (cudaStream_t)0;

    // ---- fork side stream for all per-layer prep ----
    if (streams_ok) {
        cudaEventRecord(ev_fork, 0);
        cudaStreamWaitEvent(SP, ev_fork, 0);
    }

    for (int i = 2; i >= 0; i--) {
        build_lt_upt_kernel<<<dim3((D_ + 255) / 256, D_, 2), 256, 0, SP>>>(
            lower + i * D_ * D_, upper + i * D_ * D_,
            lu_ud + i * D_, perms + i * D_, LT, UpT);
        apt_gemm_tc<<<dim3((D_ + 63) / 64, (D_ + 127) / 128), 256, 0, SP>>>(
            UpT, LT, ApT[i]);
        if (streams_ok) cudaEventRecord(ev_apt[i], SP);
        prep_weights_kernel<<<(PREP_TOTAL + 255) / 256, 256, 0, SP>>>(
            Wi + i * F_ * H_, Wb + i * 4 * H_ * H_, Wo + i * H_ * OUT_,
            wip[i], wbp[i], wop[i]);
        if (streams_ok) cudaEventRecord(ev_prep[i], SP);
        ident_knots_kernel<<<(F_ + 255) / 256, 256, 0, SP>>>(
            uw_u + i * F_ * 8, uh_u + i * F_ * 8, ud_u + i * F_ * 7, kn[i]);
        if (streams_ok) cudaEventRecord(ev_kn[i], SP);
    }

    // ---- main chain on the capture (default) stream ----
    copy_pad_kernel<<<(B_ * D_ + 255) / 256, 256>>>(x, zb0);
    zero_kernel<<<(B_ + 255) / 256, 256>>>(lq, B_);
    sumlog_kernel<<<3, 256>>>(lu_ud, slog);

    // Ping-pong: s=0: zb0->zb1; s=1: zb1->zb0; s=2: zb0->zb1. final reads zb1.
    for (int s = 0; s < 3; s++) {
        int i = 2 - s;
        const float* src = (s & 1) ? zb1 : zb0;
        float*       dst = (s & 1) ? zb0 : zb1;
        if (streams_ok) {
            cudaStreamWaitEvent(0, ev_apt[i], 0);
            cudaStreamWaitEvent(0, ev_kn[i], 0);
        }
        lu_gemm_fused<<<dim3((D_ + 63) / 64, B_ / 128), 256>>>(
            src, ApT[i], lu_b + i * D_, dst, kn[i], ident, lq);
        if (streams_ok) cudaStreamWaitEvent(0, ev_prep[i], 0);
        resnet_fused<<<B_ / 32, 256, RESNET_SMEM>>>(
            ident, wip[i], bi + i * H_, wbp[i], bb + i * 4 * H_, t);
        wo_spline_tc<<<dim3((F_ + 7) / 8, B_ / 64), 256, WOSP_SMEM>>>(
            t, wop[i], bo + i * OUT_, dst, dst, lq);
    }

    final_kernel<<<B_, 256>>>(zb1, loc, lsc, lq, slog, outp);
}